// round 1
// baseline (speedup 1.0000x reference)
#include <cuda_runtime.h>

#define N_NODES 100000
#define N_EDGES 3200000
#define HID 256
#define EMB 128
#define N_PAIRS 100000

// ---------------- scratch (device globals; no runtime allocation) -----------
__device__ float g_x [N_NODES * HID];      // node_emb + type_emb[type]
__device__ float g_ax[N_NODES * HID];      // spmm(x)
__device__ float g_h [N_NODES * HID];      // relu(ax @ W1 + b1)
__device__ float g_hw[N_NODES * EMB];      // h @ W2
__device__ float g_z [N_NODES * EMB];      // spmm(hw) + b2
__device__ float g_feat[N_PAIRS * 3 * EMB];
__device__ float g_hp[N_PAIRS * EMB];
__device__ int   g_rowptr[N_NODES + 1];

// ---------------- row_ptr from sorted rows via binary search ----------------
__global__ void build_rowptr(const int* __restrict__ rows) {
    int n = blockIdx.x * blockDim.x + threadIdx.x;
    if (n > N_NODES) return;
    int lo = 0, hi = N_EDGES;
    while (lo < hi) {
        int mid = (lo + hi) >> 1;
        if (rows[mid] < n) lo = mid + 1; else hi = mid;
    }
    g_rowptr[n] = lo;
}

// ---------------- x = node_emb + type_emb[type] (float4) --------------------
__global__ void add_emb(const float* __restrict__ node_emb,
                        const float* __restrict__ type_emb,
                        const int* __restrict__ tids) {
    int i = blockIdx.x * blockDim.x + threadIdx.x;          // float4 index
    const int NV = N_NODES * HID / 4;
    if (i >= NV) return;
    int n  = i / (HID / 4);
    int k4 = i % (HID / 4);
    int t  = tids[n];
    float4 a = reinterpret_cast<const float4*>(node_emb)[i];
    float4 b = reinterpret_cast<const float4*>(type_emb)[t * (HID / 4) + k4];
    a.x += b.x; a.y += b.y; a.z += b.z; a.w += b.w;
    reinterpret_cast<float4*>(g_x)[i] = a;
}

// ---------------- SpMM: y[n,:] = sum_e val[e] * x[col[e],:]  (+bias) --------
template <int H>
__global__ void spmm_kernel(const float* __restrict__ x, float* __restrict__ y,
                            const int* __restrict__ cols,
                            const float* __restrict__ vals,
                            const float* __restrict__ bias) {
    int n   = blockIdx.x;
    int tid = threadIdx.x;           // 0..H-1
    int e  = g_rowptr[n];
    int e1 = g_rowptr[n + 1];
    float acc = 0.f;
    // unroll-by-4: 4 independent gathered loads in flight (MLP=4)
    for (; e + 4 <= e1; e += 4) {
        int   c0 = __ldg(cols + e + 0), c1 = __ldg(cols + e + 1);
        int   c2 = __ldg(cols + e + 2), c3 = __ldg(cols + e + 3);
        float v0 = __ldg(vals + e + 0), v1 = __ldg(vals + e + 1);
        float v2 = __ldg(vals + e + 2), v3 = __ldg(vals + e + 3);
        float x0 = __ldg(x + c0 * H + tid);
        float x1 = __ldg(x + c1 * H + tid);
        float x2 = __ldg(x + c2 * H + tid);
        float x3 = __ldg(x + c3 * H + tid);
        acc += v0 * x0; acc += v1 * x1; acc += v2 * x2; acc += v3 * x3;
    }
    for (; e < e1; e++)
        acc += __ldg(vals + e) * __ldg(x + __ldg(cols + e) * H + tid);
    if (bias) acc += bias[tid];
    y[n * H + tid] = acc;
}

// ---------------- fp32 tiled GEMM: C = op(A @ B + bias), row-major ----------
// BM=128, BN=64, BK=16; 256 threads; 8x4 register tile per thread.
template <bool RELU>
__global__ void __launch_bounds__(256, 4)
gemm_kernel(const float* __restrict__ A, const float* __restrict__ B,
            float* __restrict__ C, const float* __restrict__ bias,
            int M, int K, int Nn) {
    const int BM = 128, BN = 64, BK = 16;
    __shared__ float As[BK][BM + 4];   // transposed A tile (+pad)
    __shared__ float Bs[BK][BN];

    int m0 = blockIdx.x * BM;
    int n0 = blockIdx.y * BN;
    int tid = threadIdx.x;
    int tx = tid & 15;       // column group: n0 + tx*4
    int ty = tid >> 4;       // row group:    m0 + ty*8

    float acc[8][4];
#pragma unroll
    for (int i = 0; i < 8; i++)
#pragma unroll
        for (int j = 0; j < 4; j++) acc[i][j] = 0.f;

    for (int k0 = 0; k0 < K; k0 += BK) {
        // --- load A tile (128x16), store transposed into As[k][m] ---
#pragma unroll
        for (int l = 0; l < 2; l++) {
            int idx = tid + l * 256;          // 0..511
            int row = idx >> 2;               // 0..127
            int kk  = (idx & 3) * 4;          // 0,4,8,12
            float4 v = make_float4(0.f, 0.f, 0.f, 0.f);
            if (m0 + row < M)
                v = *reinterpret_cast<const float4*>(A + (size_t)(m0 + row) * K + k0 + kk);
            As[kk + 0][row] = v.x;
            As[kk + 1][row] = v.y;
            As[kk + 2][row] = v.z;
            As[kk + 3][row] = v.w;
        }
        // --- load B tile (16x64) ---
        {
            int row = tid >> 4;               // 0..15
            int nn  = (tid & 15) * 4;         // 0..60
            *reinterpret_cast<float4*>(&Bs[row][nn]) =
                *reinterpret_cast<const float4*>(B + (size_t)(k0 + row) * Nn + n0 + nn);
        }
        __syncthreads();

#pragma unroll
        for (int k = 0; k < BK; k++) {
            float4 a0 = *reinterpret_cast<float4*>(&As[k][ty * 8]);
            float4 a1 = *reinterpret_cast<float4*>(&As[k][ty * 8 + 4]);
            float4 b  = *reinterpret_cast<float4*>(&Bs[k][tx * 4]);
            float av[8] = {a0.x, a0.y, a0.z, a0.w, a1.x, a1.y, a1.z, a1.w};
            float bv[4] = {b.x, b.y, b.z, b.w};
#pragma unroll
            for (int i = 0; i < 8; i++)
#pragma unroll
                for (int j = 0; j < 4; j++) acc[i][j] += av[i] * bv[j];
        }
        __syncthreads();
    }

    // --- epilogue: bias + relu + float4 store ---
    float4 bb = make_float4(0.f, 0.f, 0.f, 0.f);
    if (bias) bb = *reinterpret_cast<const float4*>(bias + n0 + tx * 4);
#pragma unroll
    for (int i = 0; i < 8; i++) {
        int m = m0 + ty * 8 + i;
        if (m >= M) continue;
        float4 v;
        v.x = acc[i][0] + bb.x;
        v.y = acc[i][1] + bb.y;
        v.z = acc[i][2] + bb.z;
        v.w = acc[i][3] + bb.w;
        if (RELU) {
            v.x = fmaxf(v.x, 0.f); v.y = fmaxf(v.y, 0.f);
            v.z = fmaxf(v.z, 0.f); v.w = fmaxf(v.w, 0.f);
        }
        *reinterpret_cast<float4*>(C + (size_t)m * Nn + n0 + tx * 4) = v;
    }
}

// ---------------- feat = [z[s], z[d], z[s]*z[d]] ----------------------------
__global__ void build_feat(const int* __restrict__ pairs) {
    int p = blockIdx.x;
    int j = threadIdx.x;        // 0..383
    int s = pairs[p];
    int d = pairs[N_PAIRS + p];
    float v;
    if (j < EMB)          v = g_z[s * EMB + j];
    else if (j < 2 * EMB) v = g_z[d * EMB + (j - EMB)];
    else {
        int jj = j - 2 * EMB;
        v = g_z[s * EMB + jj] * g_z[d * EMB + jj];
    }
    g_feat[(size_t)p * (3 * EMB) + j] = v;
}

// ---------------- out[p] = dot(hp[p], Wp2) + bp2 ----------------------------
__global__ void final_dot(const float* __restrict__ Wp2,
                          const float* __restrict__ bp2,
                          float* __restrict__ out) {
    int warp = (blockIdx.x * blockDim.x + threadIdx.x) >> 5;
    int lane = threadIdx.x & 31;
    if (warp >= N_PAIRS) return;
    float4 h = *reinterpret_cast<const float4*>(g_hp + (size_t)warp * EMB + lane * 4);
    float4 w = *reinterpret_cast<const float4*>(Wp2 + lane * 4);
    float s = h.x * w.x + h.y * w.y + h.z * w.z + h.w * w.w;
#pragma unroll
    for (int o = 16; o; o >>= 1) s += __shfl_xor_sync(0xffffffffu, s, o);
    if (lane == 0) out[warp] = s + bp2[0];
}

// ---------------------------------------------------------------------------
extern "C" void kernel_launch(void* const* d_in, const int* in_sizes, int n_in,
                              void* d_out, int out_size) {
    const int*   tids     = (const int*)  d_in[0];
    const int*   rows     = (const int*)  d_in[1];
    const int*   cols     = (const int*)  d_in[2];
    const float* vals     = (const float*)d_in[3];
    const int*   pairs    = (const int*)  d_in[4];
    const float* node_emb = (const float*)d_in[5];
    const float* type_emb = (const float*)d_in[6];
    const float* W1  = (const float*)d_in[7];
    const float* b1  = (const float*)d_in[8];
    const float* W2  = (const float*)d_in[9];
    const float* b2  = (const float*)d_in[10];
    const float* Wp1 = (const float*)d_in[11];
    const float* bp1 = (const float*)d_in[12];
    const float* Wp2 = (const float*)d_in[13];
    const float* bp2 = (const float*)d_in[14];
    float* out = (float*)d_out;

    void *px, *pax, *ph, *phw, *pz, *pfeat, *php;
    cudaGetSymbolAddress(&px,   g_x);
    cudaGetSymbolAddress(&pax,  g_ax);
    cudaGetSymbolAddress(&ph,   g_h);
    cudaGetSymbolAddress(&phw,  g_hw);
    cudaGetSymbolAddress(&pz,   g_z);
    cudaGetSymbolAddress(&pfeat,g_feat);
    cudaGetSymbolAddress(&php,  g_hp);

    // 1. row_ptr
    build_rowptr<<<(N_NODES + 1 + 255) / 256, 256>>>(rows);
    // 2. x = node_emb + type_emb[type]
    add_emb<<<(N_NODES * HID / 4 + 255) / 256, 256>>>(node_emb, type_emb, tids);
    // 3. ax = spmm(x)
    spmm_kernel<HID><<<N_NODES, HID>>>((const float*)px, (float*)pax, cols, vals, nullptr);
    // 4. h = relu(ax @ W1 + b1)
    {
        dim3 grid((N_NODES + 127) / 128, HID / 64);
        gemm_kernel<true><<<grid, 256>>>((const float*)pax, W1, (float*)ph, b1,
                                         N_NODES, HID, HID);
    }
    // 5. hw = h @ W2   (spmm commutes with right-mul: halves spmm2 traffic)
    {
        dim3 grid((N_NODES + 127) / 128, EMB / 64);
        gemm_kernel<false><<<grid, 256>>>((const float*)ph, W2, (float*)phw, nullptr,
                                          N_NODES, HID, EMB);
    }
    // 6. z = spmm(hw) + b2
    spmm_kernel<EMB><<<N_NODES, EMB>>>((const float*)phw, (float*)pz, cols, vals, b2);
    // 7. feat
    build_feat<<<N_PAIRS, 3 * EMB>>>(pairs);
    // 8. hp = relu(feat @ Wp1 + bp1)
    {
        dim3 grid((N_PAIRS + 127) / 128, EMB / 64);
        gemm_kernel<true><<<grid, 256>>>((const float*)pfeat, Wp1, (float*)php, bp1,
                                         N_PAIRS, 3 * EMB, EMB);
    }
    // 9. out = hp @ Wp2 + bp2
    final_dot<<<(N_PAIRS * 32 + 255) / 256, 256>>>(Wp2, bp2, out);
}

// round 3
// speedup vs baseline: 1.2711x; 1.2711x over previous
#include <cuda_runtime.h>
#include <cuda_bf16.h>
#include <cstdint>

#define N_NODES 100000
#define N_EDGES 3200000
#define HID 256
#define EMB 128
#define N_PAIRS 100000

// ===================== scratch (device globals) =============================
__device__ float g_x [N_NODES * HID];                       // spmm1 input (fp32)
__device__ __nv_bfloat16 g_ax_hi[N_NODES * HID], g_ax_lo[N_NODES * HID];
__device__ __nv_bfloat16 g_h_hi [N_NODES * HID], g_h_lo [N_NODES * HID];
__device__ float g_hw[N_NODES * EMB];                       // GEMM2 out (fp32, feeds spmm2)
__device__ float g_z [N_NODES * EMB];                       // spmm2 out
__device__ __nv_bfloat16 g_feat_hi[(size_t)N_PAIRS * 3 * EMB];
__device__ __nv_bfloat16 g_feat_lo[(size_t)N_PAIRS * 3 * EMB];
__device__ float g_hp[N_PAIRS * EMB];
__device__ int   g_rowptr[N_NODES + 1];
// transposed + bf16-split weights: [N][K]
__device__ __nv_bfloat16 g_w1hi[HID * HID],      g_w1lo[HID * HID];
__device__ __nv_bfloat16 g_w2hi[EMB * HID],      g_w2lo[EMB * HID];
__device__ __nv_bfloat16 g_wp1hi[EMB * 3 * EMB], g_wp1lo[EMB * 3 * EMB];

// ===================== helpers ==============================================
__device__ __forceinline__ uint32_t smem_u32(const void* p) {
    uint32_t a;
    asm("{ .reg .u64 t; cvta.to.shared.u64 t, %1; cvt.u32.u64 %0, t; }"
        : "=r"(a) : "l"(p));
    return a;
}
__device__ __forceinline__ void cp16(uint32_t dst, const void* src) {
    asm volatile("cp.async.cg.shared.global [%0], [%1], 16;" :: "r"(dst), "l"(src));
}
#define CP_COMMIT() asm volatile("cp.async.commit_group;" ::: "memory")
#define CP_WAIT1()  asm volatile("cp.async.wait_group 1;" ::: "memory")

__device__ __forceinline__ void ldsm4(uint32_t& r0, uint32_t& r1,
                                      uint32_t& r2, uint32_t& r3, uint32_t addr) {
    asm volatile("ldmatrix.sync.aligned.m8n8.x4.shared.b16 {%0,%1,%2,%3}, [%4];"
                 : "=r"(r0), "=r"(r1), "=r"(r2), "=r"(r3) : "r"(addr));
}
__device__ __forceinline__ void mma16816(float& d0, float& d1, float& d2, float& d3,
                                         uint32_t a0, uint32_t a1, uint32_t a2, uint32_t a3,
                                         uint32_t b0, uint32_t b1) {
    asm volatile(
        "mma.sync.aligned.m16n8k16.row.col.f32.bf16.bf16.f32 "
        "{%0,%1,%2,%3}, {%4,%5,%6,%7}, {%8,%9}, {%0,%1,%2,%3};"
        : "+f"(d0), "+f"(d1), "+f"(d2), "+f"(d3)
        : "r"(a0), "r"(a1), "r"(a2), "r"(a3), "r"(b0), "r"(b1));
}
__device__ __forceinline__ uint32_t pk_bf2(__nv_bfloat16 a, __nv_bfloat16 b) {
    __nv_bfloat162 t(a, b);
    return *reinterpret_cast<uint32_t*>(&t);
}
__device__ __forceinline__ void split_bf16(float v, __nv_bfloat16& h, __nv_bfloat16& l) {
    h = __float2bfloat16(v);
    l = __float2bfloat16(v - __bfloat162float(h));
}

// ===================== small kernels ========================================
__global__ void build_rowptr(const int* __restrict__ rows) {
    int n = blockIdx.x * blockDim.x + threadIdx.x;
    if (n > N_NODES) return;
    int lo = 0, hi = N_EDGES;
    while (lo < hi) {
        int mid = (lo + hi) >> 1;
        if (rows[mid] < n) lo = mid + 1; else hi = mid;
    }
    g_rowptr[n] = lo;
}

__global__ void add_emb(const float* __restrict__ node_emb,
                        const float* __restrict__ type_emb,
                        const int* __restrict__ tids) {
    int i = blockIdx.x * blockDim.x + threadIdx.x;
    const int NV = N_NODES * HID / 4;
    if (i >= NV) return;
    int n  = i / (HID / 4);
    int k4 = i % (HID / 4);
    int t  = tids[n];
    float4 a = reinterpret_cast<const float4*>(node_emb)[i];
    float4 b = reinterpret_cast<const float4*>(type_emb)[t * (HID / 4) + k4];
    a.x += b.x; a.y += b.y; a.z += b.z; a.w += b.w;
    reinterpret_cast<float4*>(g_x)[i] = a;
}

// W [K,N] fp32  ->  Wt_hi/Wt_lo [N,K] bf16 split
__global__ void prep_w(const float* __restrict__ W,
                       __nv_bfloat16* __restrict__ hi,
                       __nv_bfloat16* __restrict__ lo, int K, int N) {
    int i = blockIdx.x * blockDim.x + threadIdx.x;
    if (i >= K * N) return;
    int k = i / N, n = i % N;
    __nv_bfloat16 h, l;
    split_bf16(W[i], h, l);
    hi[n * K + k] = h;
    lo[n * K + k] = l;
}

// ---------------- SpMM ------------------------------------------------------
template <int H, bool SPLIT>
__global__ void spmm_kernel(const float* __restrict__ x,
                            float* __restrict__ yf,
                            __nv_bfloat16* __restrict__ yhi,
                            __nv_bfloat16* __restrict__ ylo,
                            const int* __restrict__ cols,
                            const float* __restrict__ vals,
                            const float* __restrict__ bias) {
    int n   = blockIdx.x;
    int tid = threadIdx.x;
    int e  = g_rowptr[n];
    int e1 = g_rowptr[n + 1];
    float acc = 0.f;
    for (; e + 4 <= e1; e += 4) {
        int   c0 = __ldg(cols + e + 0), c1 = __ldg(cols + e + 1);
        int   c2 = __ldg(cols + e + 2), c3 = __ldg(cols + e + 3);
        float v0 = __ldg(vals + e + 0), v1 = __ldg(vals + e + 1);
        float v2 = __ldg(vals + e + 2), v3 = __ldg(vals + e + 3);
        float x0 = __ldg(x + c0 * H + tid);
        float x1 = __ldg(x + c1 * H + tid);
        float x2 = __ldg(x + c2 * H + tid);
        float x3 = __ldg(x + c3 * H + tid);
        acc += v0 * x0; acc += v1 * x1; acc += v2 * x2; acc += v3 * x3;
    }
    for (; e < e1; e++)
        acc += __ldg(vals + e) * __ldg(x + __ldg(cols + e) * H + tid);
    if (bias) acc += bias[tid];
    if (SPLIT) {
        __nv_bfloat16 h, l;
        split_bf16(acc, h, l);
        yhi[(size_t)n * H + tid] = h;
        ylo[(size_t)n * H + tid] = l;
    } else {
        yf[(size_t)n * H + tid] = acc;
    }
}

// ===================== HMMA GEMM (3x bf16-split) ============================
// C[M, NTOT] = A[M, KTOT] @ W^T  (A, W given as bf16 hi/lo; W is [NTOT, KTOT])
// CTA: 128(M) x 64(N), 8 warps in 4(M) x 2(N), warp tile 32x32, kc=32,
// 2-stage cp.async pipeline. MODE: 0 = fp32 out; 1 = bias+relu split-bf16 out;
// 2 = bias+relu fp32 out.
template <int KTOT, int NTOT, int MODE>
__global__ void __launch_bounds__(256, 2)
gemm_mma(const __nv_bfloat16* __restrict__ Ahi,
         const __nv_bfloat16* __restrict__ Alo,
         const __nv_bfloat16* __restrict__ Whi,
         const __nv_bfloat16* __restrict__ Wlo,
         float* __restrict__ Cf,
         __nv_bfloat16* __restrict__ Chi,
         __nv_bfloat16* __restrict__ Clo,
         const float* __restrict__ bias, int M) {
    constexpr int KC = 32;
    constexpr int NS = KTOT / KC;
    constexpr int ST_AH = 0;                 // per-stage offsets (bytes)
    constexpr int ST_AL = 128 * 64;          // 8192
    constexpr int ST_WH = 2 * 128 * 64;      // 16384
    constexpr int ST_WL = 2 * 128 * 64 + 64 * 64;  // 20480
    constexpr int STAGE = 24576;

    extern __shared__ __align__(128) char smem[];
    const uint32_t sb = smem_u32(smem);

    const int tid  = threadIdx.x;
    const int lane = tid & 31;
    const int wm   = (tid >> 5) & 3;
    const int wn   = tid >> 7;
    const int m0   = blockIdx.x * 128;
    const int n0   = blockIdx.y * 64;

    // ---- stage loader ----
    auto load_stage = [&](int ks) {
        const int k0 = ks * KC;
        const uint32_t base = sb + (uint32_t)(ks & 1) * STAGE;
#pragma unroll
        for (int i = 0; i < 2; i++) {
            int id  = tid + i * 256;         // 0..511
            int row = id >> 2;
            int c   = id & 3;
            int rowg = min(m0 + row, M - 1);
            uint32_t soff = (uint32_t)(row * 64 + ((c ^ ((row >> 1) & 3)) << 4));
            size_t goff = (size_t)rowg * KTOT + k0 + c * 8;
            cp16(base + ST_AH + soff, Ahi + goff);
            cp16(base + ST_AL + soff, Alo + goff);
        }
        {
            int row = tid >> 2;
            int c   = tid & 3;
            uint32_t soff = (uint32_t)(row * 64 + ((c ^ ((row >> 1) & 3)) << 4));
            size_t goff = (size_t)(n0 + row) * KTOT + k0 + c * 8;
            cp16(base + ST_WH + soff, Whi + goff);
            cp16(base + ST_WL + soff, Wlo + goff);
        }
    };

    float acc[2][4][4];
#pragma unroll
    for (int a = 0; a < 2; a++)
#pragma unroll
        for (int b = 0; b < 4; b++)
#pragma unroll
            for (int c = 0; c < 4; c++) acc[a][b][c] = 0.f;

    // per-lane ldmatrix row geometry
    const int lrow  = (lane & 7) + ((lane >> 3) & 1) * 8;   // 0..15
    const int khalf = lane >> 4;                            // 0/1

    load_stage(0);
    CP_COMMIT();

    for (int ks = 0; ks < NS; ks++) {
        if (ks + 1 < NS) load_stage(ks + 1);
        CP_COMMIT();
        CP_WAIT1();
        __syncthreads();

        const uint32_t base = sb + (uint32_t)(ks & 1) * STAGE;
#pragma unroll
        for (int kk = 0; kk < 2; kk++) {
            const int c = kk * 2 + khalf;
            // A frags (hi/lo), 2 m16 tiles
            uint32_t ah[2][4], al[2][4];
#pragma unroll
            for (int mi = 0; mi < 2; mi++) {
                int row = wm * 32 + mi * 16 + lrow;
                uint32_t off = (uint32_t)(row * 64 + ((c ^ ((row >> 1) & 3)) << 4));
                ldsm4(ah[mi][0], ah[mi][1], ah[mi][2], ah[mi][3], base + ST_AH + off);
                ldsm4(al[mi][0], al[mi][1], al[mi][2], al[mi][3], base + ST_AL + off);
            }
            // W frags (hi/lo), 2 n16 groups
            uint32_t bh[2][4], bl[2][4];
#pragma unroll
            for (int ng = 0; ng < 2; ng++) {
                int row = wn * 32 + ng * 16 + lrow;
                uint32_t off = (uint32_t)(row * 64 + ((c ^ ((row >> 1) & 3)) << 4));
                ldsm4(bh[ng][0], bh[ng][1], bh[ng][2], bh[ng][3], base + ST_WH + off);
                ldsm4(bl[ng][0], bl[ng][1], bl[ng][2], bl[ng][3], base + ST_WL + off);
            }
            // 3 products: hi*hi, hi*lo, lo*hi
#pragma unroll
            for (int mi = 0; mi < 2; mi++)
#pragma unroll
                for (int ng = 0; ng < 2; ng++)
#pragma unroll
                    for (int sub = 0; sub < 2; sub++) {
                        int ni = ng * 2 + sub;
                        float* d = acc[mi][ni];
                        uint32_t b0h = bh[ng][sub], b1h = bh[ng][sub + 2];
                        uint32_t b0l = bl[ng][sub], b1l = bl[ng][sub + 2];
                        mma16816(d[0], d[1], d[2], d[3],
                                 ah[mi][0], ah[mi][1], ah[mi][2], ah[mi][3], b0h, b1h);
                        mma16816(d[0], d[1], d[2], d[3],
                                 ah[mi][0], ah[mi][1], ah[mi][2], ah[mi][3], b0l, b1l);
                        mma16816(d[0], d[1], d[2], d[3],
                                 al[mi][0], al[mi][1], al[mi][2], al[mi][3], b0h, b1h);
                    }
        }
        __syncthreads();
    }

    // ---- epilogue ----
#pragma unroll
    for (int mi = 0; mi < 2; mi++) {
        int r0 = m0 + wm * 32 + mi * 16 + (lane >> 2);
        int r1 = r0 + 8;
#pragma unroll
        for (int ni = 0; ni < 4; ni++) {
            int col = n0 + wn * 32 + ni * 8 + 2 * (lane & 3);
            float b0v = 0.f, b1v = 0.f;
            if (MODE != 0 && bias) {
                b0v = __ldg(bias + col);
                b1v = __ldg(bias + col + 1);
            }
            float v0 = acc[mi][ni][0], v1 = acc[mi][ni][1];
            float v2 = acc[mi][ni][2], v3 = acc[mi][ni][3];
            if (MODE != 0) {
                v0 = fmaxf(v0 + b0v, 0.f); v1 = fmaxf(v1 + b1v, 0.f);
                v2 = fmaxf(v2 + b0v, 0.f); v3 = fmaxf(v3 + b1v, 0.f);
            }
            if (MODE == 1) {
                __nv_bfloat16 h0, l0, h1, l1;
                if (r0 < M) {
                    split_bf16(v0, h0, l0); split_bf16(v1, h1, l1);
                    *reinterpret_cast<uint32_t*>(Chi + (size_t)r0 * NTOT + col) = pk_bf2(h0, h1);
                    *reinterpret_cast<uint32_t*>(Clo + (size_t)r0 * NTOT + col) = pk_bf2(l0, l1);
                }
                if (r1 < M) {
                    split_bf16(v2, h0, l0); split_bf16(v3, h1, l1);
                    *reinterpret_cast<uint32_t*>(Chi + (size_t)r1 * NTOT + col) = pk_bf2(h0, h1);
                    *reinterpret_cast<uint32_t*>(Clo + (size_t)r1 * NTOT + col) = pk_bf2(l0, l1);
                }
            } else {
                if (r0 < M)
                    *reinterpret_cast<float2*>(Cf + (size_t)r0 * NTOT + col) = make_float2(v0, v1);
                if (r1 < M)
                    *reinterpret_cast<float2*>(Cf + (size_t)r1 * NTOT + col) = make_float2(v2, v3);
            }
        }
    }
}

// ---------------- feat = [z[s], z[d], z[s]*z[d]] (split bf16) ---------------
__global__ void build_feat(const int* __restrict__ pairs) {
    int p = blockIdx.x;
    int j = threadIdx.x;
    int s = pairs[p];
    int d = pairs[N_PAIRS + p];
    float v;
    if (j < EMB)          v = g_z[s * EMB + j];
    else if (j < 2 * EMB) v = g_z[d * EMB + (j - EMB)];
    else {
        int jj = j - 2 * EMB;
        v = g_z[s * EMB + jj] * g_z[d * EMB + jj];
    }
    __nv_bfloat16 h, l;
    split_bf16(v, h, l);
    g_feat_hi[(size_t)p * (3 * EMB) + j] = h;
    g_feat_lo[(size_t)p * (3 * EMB) + j] = l;
}

__global__ void final_dot(const float* __restrict__ Wp2,
                          const float* __restrict__ bp2,
                          float* __restrict__ out) {
    int warp = (blockIdx.x * blockDim.x + threadIdx.x) >> 5;
    int lane = threadIdx.x & 31;
    if (warp >= N_PAIRS) return;
    float4 h = *reinterpret_cast<const float4*>(g_hp + (size_t)warp * EMB + lane * 4);
    float4 w = *reinterpret_cast<const float4*>(Wp2 + lane * 4);
    float s = h.x * w.x + h.y * w.y + h.z * w.z + h.w * w.w;
#pragma unroll
    for (int o = 16; o; o >>= 1) s += __shfl_xor_sync(0xffffffffu, s, o);
    if (lane == 0) out[warp] = s + bp2[0];
}

// ===========================================================================
extern "C" void kernel_launch(void* const* d_in, const int* in_sizes, int n_in,
                              void* d_out, int out_size) {
    const int*   tids     = (const int*)  d_in[0];
    const int*   rows     = (const int*)  d_in[1];
    const int*   cols     = (const int*)  d_in[2];
    const float* vals     = (const float*)d_in[3];
    const int*   pairs    = (const int*)  d_in[4];
    const float* node_emb = (const float*)d_in[5];
    const float* type_emb = (const float*)d_in[6];
    const float* W1  = (const float*)d_in[7];
    const float* b1  = (const float*)d_in[8];
    const float* W2  = (const float*)d_in[9];
    const float* b2  = (const float*)d_in[10];
    const float* Wp1 = (const float*)d_in[11];
    const float* bp1 = (const float*)d_in[12];
    const float* Wp2 = (const float*)d_in[13];
    const float* bp2 = (const float*)d_in[14];
    float* out = (float*)d_out;

    void *px, *paxh, *paxl, *phh, *phl, *phw, *pz, *pfh, *pfl, *php;
    void *w1h, *w1l, *w2h, *w2l, *wp1h, *wp1l;
    cudaGetSymbolAddress(&px,   g_x);
    cudaGetSymbolAddress(&paxh, g_ax_hi);  cudaGetSymbolAddress(&paxl, g_ax_lo);
    cudaGetSymbolAddress(&phh,  g_h_hi);   cudaGetSymbolAddress(&phl,  g_h_lo);
    cudaGetSymbolAddress(&phw,  g_hw);
    cudaGetSymbolAddress(&pz,   g_z);
    cudaGetSymbolAddress(&pfh,  g_feat_hi); cudaGetSymbolAddress(&pfl, g_feat_lo);
    cudaGetSymbolAddress(&php,  g_hp);
    cudaGetSymbolAddress(&w1h,  g_w1hi);  cudaGetSymbolAddress(&w1l, g_w1lo);
    cudaGetSymbolAddress(&w2h,  g_w2hi);  cudaGetSymbolAddress(&w2l, g_w2lo);
    cudaGetSymbolAddress(&wp1h, g_wp1hi); cudaGetSymbolAddress(&wp1l, g_wp1lo);

    constexpr int SMEM = 2 * 24576;   // 48 KB
    cudaFuncSetAttribute(gemm_mma<256, 256, 1>,
                         cudaFuncAttributeMaxDynamicSharedMemorySize, SMEM);
    cudaFuncSetAttribute(gemm_mma<256, 128, 0>,
                         cudaFuncAttributeMaxDynamicSharedMemorySize, SMEM);
    cudaFuncSetAttribute(gemm_mma<384, 128, 2>,
                         cudaFuncAttributeMaxDynamicSharedMemorySize, SMEM);

    // 0. weight prep (transpose + bf16 split)
    prep_w<<<(HID * HID + 255) / 256, 256>>>(W1, (__nv_bfloat16*)w1h, (__nv_bfloat16*)w1l, HID, HID);
    prep_w<<<(HID * EMB + 255) / 256, 256>>>(W2, (__nv_bfloat16*)w2h, (__nv_bfloat16*)w2l, HID, EMB);
    prep_w<<<(3 * EMB * EMB + 255) / 256, 256>>>(Wp1, (__nv_bfloat16*)wp1h, (__nv_bfloat16*)wp1l, 3 * EMB, EMB);

    // 1. row_ptr
    build_rowptr<<<(N_NODES + 1 + 255) / 256, 256>>>(rows);
    // 2. x = node_emb + type_emb[type]
    add_emb<<<(N_NODES * HID / 4 + 255) / 256, 256>>>(node_emb, type_emb, tids);
    // 3. ax = spmm(x) -> split bf16
    spmm_kernel<HID, true><<<N_NODES, HID>>>(
        (const float*)px, nullptr, (__nv_bfloat16*)paxh, (__nv_bfloat16*)paxl,
        cols, vals, nullptr);
    // 4. h = relu(ax @ W1 + b1) -> split bf16   [HMMA]
    {
        dim3 grid((N_NODES + 127) / 128, HID / 64);
        gemm_mma<256, 256, 1><<<grid, 256, SMEM>>>(
            (const __nv_bfloat16*)paxh, (const __nv_bfloat16*)paxl,
            (const __nv_bfloat16*)w1h,  (const __nv_bfloat16*)w1l,
            nullptr, (__nv_bfloat16*)phh, (__nv_bfloat16*)phl, b1, N_NODES);
    }
    // 5. hw = h @ W2  (fp32 out)   [HMMA]
    {
        dim3 grid((N_NODES + 127) / 128, EMB / 64);
        gemm_mma<256, 128, 0><<<grid, 256, SMEM>>>(
            (const __nv_bfloat16*)phh, (const __nv_bfloat16*)phl,
            (const __nv_bfloat16*)w2h, (const __nv_bfloat16*)w2l,
            (float*)phw, nullptr, nullptr, nullptr, N_NODES);
    }
    // 6. z = spmm(hw) + b2   (fp32)
    spmm_kernel<EMB, false><<<N_NODES, EMB>>>(
        (const float*)phw, (float*)pz, nullptr, nullptr, cols, vals, b2);
    // 7. feat (split bf16)
    build_feat<<<N_PAIRS, 3 * EMB>>>(pairs);
    // 8. hp = relu(feat @ Wp1 + bp1)  (fp32 out)   [HMMA]
    {
        dim3 grid((N_PAIRS + 127) / 128, EMB / 64);
        gemm_mma<384, 128, 2><<<grid, 256, SMEM>>>(
            (const __nv_bfloat16*)pfh,  (const __nv_bfloat16*)pfl,
            (const __nv_bfloat16*)wp1h, (const __nv_bfloat16*)wp1l,
            (float*)php, nullptr, nullptr, bp1, N_PAIRS);
    }
    // 9. out
    final_dot<<<(N_PAIRS * 32 + 255) / 256, 256>>>(Wp2, bp2, out);
}

// round 4
// speedup vs baseline: 1.8394x; 1.4472x over previous
#include <cuda_runtime.h>
#include <cuda_bf16.h>
#include <cuda_fp16.h>
#include <cstdint>

#define N_NODES 100000
#define N_EDGES 3200000
#define HID 256
#define EMB 128
#define N_PAIRS 100000

// ===================== scratch (device globals) =============================
__device__ __half g_xh[N_NODES * HID];                      // spmm1 input (fp16)
__device__ __nv_bfloat16 g_ax_hi[N_NODES * HID], g_ax_lo[N_NODES * HID];
__device__ __nv_bfloat16 g_h_hi [N_NODES * HID], g_h_lo [N_NODES * HID];
__device__ __half g_hwh[N_NODES * EMB];                     // GEMM2 out (fp16, feeds spmm2)
__device__ float g_z [N_NODES * EMB];                       // spmm2 out
__device__ __nv_bfloat16 g_feat_hi[(size_t)N_PAIRS * 3 * EMB];
__device__ __nv_bfloat16 g_feat_lo[(size_t)N_PAIRS * 3 * EMB];
__device__ float g_hp[N_PAIRS * EMB];
__device__ int   g_rowptr[N_NODES + 1];
// transposed + bf16-split weights: [N][K]
__device__ __nv_bfloat16 g_w1hi[HID * HID],      g_w1lo[HID * HID];
__device__ __nv_bfloat16 g_w2hi[EMB * HID],      g_w2lo[EMB * HID];
__device__ __nv_bfloat16 g_wp1hi[EMB * 3 * EMB], g_wp1lo[EMB * 3 * EMB];

// ===================== helpers ==============================================
__device__ __forceinline__ uint32_t smem_u32(const void* p) {
    uint32_t a;
    asm("{ .reg .u64 t; cvta.to.shared.u64 t, %1; cvt.u32.u64 %0, t; }"
        : "=r"(a) : "l"(p));
    return a;
}
__device__ __forceinline__ void cp16(uint32_t dst, const void* src) {
    asm volatile("cp.async.cg.shared.global [%0], [%1], 16;" :: "r"(dst), "l"(src));
}
#define CP_COMMIT() asm volatile("cp.async.commit_group;" ::: "memory")
#define CP_WAIT1()  asm volatile("cp.async.wait_group 1;" ::: "memory")

__device__ __forceinline__ void ldsm4(uint32_t& r0, uint32_t& r1,
                                      uint32_t& r2, uint32_t& r3, uint32_t addr) {
    asm volatile("ldmatrix.sync.aligned.m8n8.x4.shared.b16 {%0,%1,%2,%3}, [%4];"
                 : "=r"(r0), "=r"(r1), "=r"(r2), "=r"(r3) : "r"(addr));
}
__device__ __forceinline__ void mma16816(float& d0, float& d1, float& d2, float& d3,
                                         uint32_t a0, uint32_t a1, uint32_t a2, uint32_t a3,
                                         uint32_t b0, uint32_t b1) {
    asm volatile(
        "mma.sync.aligned.m16n8k16.row.col.f32.bf16.bf16.f32 "
        "{%0,%1,%2,%3}, {%4,%5,%6,%7}, {%8,%9}, {%0,%1,%2,%3};"
        : "+f"(d0), "+f"(d1), "+f"(d2), "+f"(d3)
        : "r"(a0), "r"(a1), "r"(a2), "r"(a3), "r"(b0), "r"(b1));
}
__device__ __forceinline__ uint32_t pk_bf2(__nv_bfloat16 a, __nv_bfloat16 b) {
    __nv_bfloat162 t(a, b);
    return *reinterpret_cast<uint32_t*>(&t);
}
__device__ __forceinline__ void split_bf16(float v, __nv_bfloat16& h, __nv_bfloat16& l) {
    h = __float2bfloat16(v);
    l = __float2bfloat16(v - __bfloat162float(h));
}

// ===================== small kernels ========================================
__global__ void build_rowptr(const int* __restrict__ rows) {
    int n = blockIdx.x * blockDim.x + threadIdx.x;
    if (n > N_NODES) return;
    int lo = 0, hi = N_EDGES;
    while (lo < hi) {
        int mid = (lo + hi) >> 1;
        if (rows[mid] < n) lo = mid + 1; else hi = mid;
    }
    g_rowptr[n] = lo;
}

// x = fp16(node_emb + type_emb[type])
__global__ void add_emb(const float* __restrict__ node_emb,
                        const float* __restrict__ type_emb,
                        const int* __restrict__ tids) {
    int i = blockIdx.x * blockDim.x + threadIdx.x;          // float4 index
    const int NV = N_NODES * HID / 4;
    if (i >= NV) return;
    int n  = i / (HID / 4);
    int k4 = i % (HID / 4);
    int t  = tids[n];
    float4 a = reinterpret_cast<const float4*>(node_emb)[i];
    float4 b = reinterpret_cast<const float4*>(type_emb)[t * (HID / 4) + k4];
    __half2 h0 = __floats2half2_rn(a.x + b.x, a.y + b.y);
    __half2 h1 = __floats2half2_rn(a.z + b.z, a.w + b.w);
    reinterpret_cast<uint2*>(g_xh)[i] =
        make_uint2(*reinterpret_cast<uint32_t*>(&h0), *reinterpret_cast<uint32_t*>(&h1));
}

// W [K,N] fp32  ->  Wt_hi/Wt_lo [N,K] bf16 split
__global__ void prep_w(const float* __restrict__ W,
                       __nv_bfloat16* __restrict__ hi,
                       __nv_bfloat16* __restrict__ lo, int K, int N) {
    int i = blockIdx.x * blockDim.x + threadIdx.x;
    if (i >= K * N) return;
    int k = i / N, n = i % N;
    __nv_bfloat16 h, l;
    split_bf16(W[i], h, l);
    hi[n * K + k] = h;
    lo[n * K + k] = l;
}

// ---------------- SpMM (fp16 gather, fp32 accumulate) -----------------------
// One node per block, H/2 threads, each owns one half2 column pair.
// OUT: 0 = fp32 (+bias), 1 = split bf16.
template <int H, int OUT>
__global__ void spmm_h2(const __half2* __restrict__ x,
                        float* __restrict__ yf,
                        __nv_bfloat16* __restrict__ yhi,
                        __nv_bfloat16* __restrict__ ylo,
                        const int* __restrict__ cols,
                        const float* __restrict__ vals,
                        const float* __restrict__ bias) {
    constexpr int H2 = H / 2;
    int n   = blockIdx.x;
    int t   = threadIdx.x;          // 0..H2-1
    int e  = g_rowptr[n];
    int e1 = g_rowptr[n + 1];
    float ax = 0.f, ay = 0.f;
    for (; e + 4 <= e1; e += 4) {
        int   c0 = __ldg(cols + e + 0), c1 = __ldg(cols + e + 1);
        int   c2 = __ldg(cols + e + 2), c3 = __ldg(cols + e + 3);
        float v0 = __ldg(vals + e + 0), v1 = __ldg(vals + e + 1);
        float v2 = __ldg(vals + e + 2), v3 = __ldg(vals + e + 3);
        float2 x0 = __half22float2(__ldg(x + (size_t)c0 * H2 + t));
        float2 x1 = __half22float2(__ldg(x + (size_t)c1 * H2 + t));
        float2 x2 = __half22float2(__ldg(x + (size_t)c2 * H2 + t));
        float2 x3 = __half22float2(__ldg(x + (size_t)c3 * H2 + t));
        ax += v0 * x0.x; ay += v0 * x0.y;
        ax += v1 * x1.x; ay += v1 * x1.y;
        ax += v2 * x2.x; ay += v2 * x2.y;
        ax += v3 * x3.x; ay += v3 * x3.y;
    }
    for (; e < e1; e++) {
        float v = __ldg(vals + e);
        float2 xv = __half22float2(__ldg(x + (size_t)__ldg(cols + e) * H2 + t));
        ax += v * xv.x; ay += v * xv.y;
    }
    if (OUT == 0) {
        if (bias) { ax += bias[2 * t]; ay += bias[2 * t + 1]; }
        *reinterpret_cast<float2*>(yf + (size_t)n * H + 2 * t) = make_float2(ax, ay);
    } else {
        __nv_bfloat16 h0, l0, h1, l1;
        split_bf16(ax, h0, l0);
        split_bf16(ay, h1, l1);
        *reinterpret_cast<uint32_t*>(yhi + (size_t)n * H + 2 * t) = pk_bf2(h0, h1);
        *reinterpret_cast<uint32_t*>(ylo + (size_t)n * H + 2 * t) = pk_bf2(l0, l1);
    }
}

// ===================== HMMA GEMM (3x bf16-split) ============================
// C[M, NTOT] = A[M, KTOT] @ W^T  (A, W given as bf16 hi/lo; W is [NTOT, KTOT])
// CTA: 128(M) x 64(N), 8 warps 4x2, warp tile 32x32, kc=32, 2-stage cp.async.
// MODE: 0 = fp32 out; 1 = bias+relu split-bf16 out; 2 = bias+relu fp32 out;
//       3 = fp16 out.
template <int KTOT, int NTOT, int MODE>
__global__ void __launch_bounds__(256, 2)
gemm_mma(const __nv_bfloat16* __restrict__ Ahi,
         const __nv_bfloat16* __restrict__ Alo,
         const __nv_bfloat16* __restrict__ Whi,
         const __nv_bfloat16* __restrict__ Wlo,
         float* __restrict__ Cf,
         __nv_bfloat16* __restrict__ Chi,
         __nv_bfloat16* __restrict__ Clo,
         __half* __restrict__ Ch,
         const float* __restrict__ bias, int M) {
    constexpr int KC = 32;
    constexpr int NS = KTOT / KC;
    constexpr int ST_AH = 0;
    constexpr int ST_AL = 128 * 64;
    constexpr int ST_WH = 2 * 128 * 64;
    constexpr int ST_WL = 2 * 128 * 64 + 64 * 64;
    constexpr int STAGE = 24576;

    extern __shared__ __align__(128) char smem[];
    const uint32_t sb = smem_u32(smem);

    const int tid  = threadIdx.x;
    const int lane = tid & 31;
    const int wm   = (tid >> 5) & 3;
    const int wn   = tid >> 7;
    const int m0   = blockIdx.x * 128;
    const int n0   = blockIdx.y * 64;

    auto load_stage = [&](int ks) {
        const int k0 = ks * KC;
        const uint32_t base = sb + (uint32_t)(ks & 1) * STAGE;
#pragma unroll
        for (int i = 0; i < 2; i++) {
            int id  = tid + i * 256;
            int row = id >> 2;
            int c   = id & 3;
            int rowg = min(m0 + row, M - 1);
            uint32_t soff = (uint32_t)(row * 64 + ((c ^ ((row >> 1) & 3)) << 4));
            size_t goff = (size_t)rowg * KTOT + k0 + c * 8;
            cp16(base + ST_AH + soff, Ahi + goff);
            cp16(base + ST_AL + soff, Alo + goff);
        }
        {
            int row = tid >> 2;
            int c   = tid & 3;
            uint32_t soff = (uint32_t)(row * 64 + ((c ^ ((row >> 1) & 3)) << 4));
            size_t goff = (size_t)(n0 + row) * KTOT + k0 + c * 8;
            cp16(base + ST_WH + soff, Whi + goff);
            cp16(base + ST_WL + soff, Wlo + goff);
        }
    };

    float acc[2][4][4];
#pragma unroll
    for (int a = 0; a < 2; a++)
#pragma unroll
        for (int b = 0; b < 4; b++)
#pragma unroll
            for (int c = 0; c < 4; c++) acc[a][b][c] = 0.f;

    const int lrow  = (lane & 7) + ((lane >> 3) & 1) * 8;
    const int khalf = lane >> 4;

    load_stage(0);
    CP_COMMIT();

    for (int ks = 0; ks < NS; ks++) {
        if (ks + 1 < NS) load_stage(ks + 1);
        CP_COMMIT();
        CP_WAIT1();
        __syncthreads();

        const uint32_t base = sb + (uint32_t)(ks & 1) * STAGE;
#pragma unroll
        for (int kk = 0; kk < 2; kk++) {
            const int c = kk * 2 + khalf;
            uint32_t ah[2][4], al[2][4];
#pragma unroll
            for (int mi = 0; mi < 2; mi++) {
                int row = wm * 32 + mi * 16 + lrow;
                uint32_t off = (uint32_t)(row * 64 + ((c ^ ((row >> 1) & 3)) << 4));
                ldsm4(ah[mi][0], ah[mi][1], ah[mi][2], ah[mi][3], base + ST_AH + off);
                ldsm4(al[mi][0], al[mi][1], al[mi][2], al[mi][3], base + ST_AL + off);
            }
            uint32_t bh[2][4], bl[2][4];
#pragma unroll
            for (int ng = 0; ng < 2; ng++) {
                int row = wn * 32 + ng * 16 + lrow;
                uint32_t off = (uint32_t)(row * 64 + ((c ^ ((row >> 1) & 3)) << 4));
                ldsm4(bh[ng][0], bh[ng][1], bh[ng][2], bh[ng][3], base + ST_WH + off);
                ldsm4(bl[ng][0], bl[ng][1], bl[ng][2], bl[ng][3], base + ST_WL + off);
            }
#pragma unroll
            for (int mi = 0; mi < 2; mi++)
#pragma unroll
                for (int ng = 0; ng < 2; ng++)
#pragma unroll
                    for (int sub = 0; sub < 2; sub++) {
                        int ni = ng * 2 + sub;
                        float* d = acc[mi][ni];
                        uint32_t b0h = bh[ng][sub], b1h = bh[ng][sub + 2];
                        uint32_t b0l = bl[ng][sub], b1l = bl[ng][sub + 2];
                        mma16816(d[0], d[1], d[2], d[3],
                                 ah[mi][0], ah[mi][1], ah[mi][2], ah[mi][3], b0h, b1h);
                        mma16816(d[0], d[1], d[2], d[3],
                                 ah[mi][0], ah[mi][1], ah[mi][2], ah[mi][3], b0l, b1l);
                        mma16816(d[0], d[1], d[2], d[3],
                                 al[mi][0], al[mi][1], al[mi][2], al[mi][3], b0h, b1h);
                    }
        }
        __syncthreads();
    }

    // ---- epilogue ----
#pragma unroll
    for (int mi = 0; mi < 2; mi++) {
        int r0 = m0 + wm * 32 + mi * 16 + (lane >> 2);
        int r1 = r0 + 8;
#pragma unroll
        for (int ni = 0; ni < 4; ni++) {
            int col = n0 + wn * 32 + ni * 8 + 2 * (lane & 3);
            float b0v = 0.f, b1v = 0.f;
            if ((MODE == 1 || MODE == 2) && bias) {
                b0v = __ldg(bias + col);
                b1v = __ldg(bias + col + 1);
            }
            float v0 = acc[mi][ni][0], v1 = acc[mi][ni][1];
            float v2 = acc[mi][ni][2], v3 = acc[mi][ni][3];
            if (MODE == 1 || MODE == 2) {
                v0 = fmaxf(v0 + b0v, 0.f); v1 = fmaxf(v1 + b1v, 0.f);
                v2 = fmaxf(v2 + b0v, 0.f); v3 = fmaxf(v3 + b1v, 0.f);
            }
            if (MODE == 1) {
                __nv_bfloat16 h0, l0, h1, l1;
                if (r0 < M) {
                    split_bf16(v0, h0, l0); split_bf16(v1, h1, l1);
                    *reinterpret_cast<uint32_t*>(Chi + (size_t)r0 * NTOT + col) = pk_bf2(h0, h1);
                    *reinterpret_cast<uint32_t*>(Clo + (size_t)r0 * NTOT + col) = pk_bf2(l0, l1);
                }
                if (r1 < M) {
                    split_bf16(v2, h0, l0); split_bf16(v3, h1, l1);
                    *reinterpret_cast<uint32_t*>(Chi + (size_t)r1 * NTOT + col) = pk_bf2(h0, h1);
                    *reinterpret_cast<uint32_t*>(Clo + (size_t)r1 * NTOT + col) = pk_bf2(l0, l1);
                }
            } else if (MODE == 3) {
                if (r0 < M) {
                    __half2 p = __floats2half2_rn(v0, v1);
                    *reinterpret_cast<uint32_t*>(Ch + (size_t)r0 * NTOT + col) =
                        *reinterpret_cast<uint32_t*>(&p);
                }
                if (r1 < M) {
                    __half2 p = __floats2half2_rn(v2, v3);
                    *reinterpret_cast<uint32_t*>(Ch + (size_t)r1 * NTOT + col) =
                        *reinterpret_cast<uint32_t*>(&p);
                }
            } else {
                if (r0 < M)
                    *reinterpret_cast<float2*>(Cf + (size_t)r0 * NTOT + col) = make_float2(v0, v1);
                if (r1 < M)
                    *reinterpret_cast<float2*>(Cf + (size_t)r1 * NTOT + col) = make_float2(v2, v3);
            }
        }
    }
}

// ---------------- feat = [z[s], z[d], z[s]*z[d]] (split bf16) ---------------
__global__ void build_feat(const int* __restrict__ pairs) {
    int p = blockIdx.x;
    int j = threadIdx.x;
    int s = pairs[p];
    int d = pairs[N_PAIRS + p];
    float v;
    if (j < EMB)          v = g_z[s * EMB + j];
    else if (j < 2 * EMB) v = g_z[d * EMB + (j - EMB)];
    else {
        int jj = j - 2 * EMB;
        v = g_z[s * EMB + jj] * g_z[d * EMB + jj];
    }
    __nv_bfloat16 h, l;
    split_bf16(v, h, l);
    g_feat_hi[(size_t)p * (3 * EMB) + j] = h;
    g_feat_lo[(size_t)p * (3 * EMB) + j] = l;
}

__global__ void final_dot(const float* __restrict__ Wp2,
                          const float* __restrict__ bp2,
                          float* __restrict__ out) {
    int warp = (blockIdx.x * blockDim.x + threadIdx.x) >> 5;
    int lane = threadIdx.x & 31;
    if (warp >= N_PAIRS) return;
    float4 h = *reinterpret_cast<const float4*>(g_hp + (size_t)warp * EMB + lane * 4);
    float4 w = *reinterpret_cast<const float4*>(Wp2 + lane * 4);
    float s = h.x * w.x + h.y * w.y + h.z * w.z + h.w * w.w;
#pragma unroll
    for (int o = 16; o; o >>= 1) s += __shfl_xor_sync(0xffffffffu, s, o);
    if (lane == 0) out[warp] = s + bp2[0];
}

// ===========================================================================
extern "C" void kernel_launch(void* const* d_in, const int* in_sizes, int n_in,
                              void* d_out, int out_size) {
    const int*   tids     = (const int*)  d_in[0];
    const int*   rows     = (const int*)  d_in[1];
    const int*   cols     = (const int*)  d_in[2];
    const float* vals     = (const float*)d_in[3];
    const int*   pairs    = (const int*)  d_in[4];
    const float* node_emb = (const float*)d_in[5];
    const float* type_emb = (const float*)d_in[6];
    const float* W1  = (const float*)d_in[7];
    const float* b1  = (const float*)d_in[8];
    const float* W2  = (const float*)d_in[9];
    const float* b2  = (const float*)d_in[10];
    const float* Wp1 = (const float*)d_in[11];
    const float* bp1 = (const float*)d_in[12];
    const float* Wp2 = (const float*)d_in[13];
    const float* bp2 = (const float*)d_in[14];
    float* out = (float*)d_out;

    void *pxh, *paxh, *paxl, *phh, *phl, *phwh, *pz, *pfh, *pfl, *php;
    void *w1h, *w1l, *w2h, *w2l, *wp1h, *wp1l;
    cudaGetSymbolAddress(&pxh,  g_xh);
    cudaGetSymbolAddress(&paxh, g_ax_hi);  cudaGetSymbolAddress(&paxl, g_ax_lo);
    cudaGetSymbolAddress(&phh,  g_h_hi);   cudaGetSymbolAddress(&phl,  g_h_lo);
    cudaGetSymbolAddress(&phwh, g_hwh);
    cudaGetSymbolAddress(&pz,   g_z);
    cudaGetSymbolAddress(&pfh,  g_feat_hi); cudaGetSymbolAddress(&pfl, g_feat_lo);
    cudaGetSymbolAddress(&php,  g_hp);
    cudaGetSymbolAddress(&w1h,  g_w1hi);  cudaGetSymbolAddress(&w1l, g_w1lo);
    cudaGetSymbolAddress(&w2h,  g_w2hi);  cudaGetSymbolAddress(&w2l, g_w2lo);
    cudaGetSymbolAddress(&wp1h, g_wp1hi); cudaGetSymbolAddress(&wp1l, g_wp1lo);

    constexpr int SMEM = 2 * 24576;   // 48 KB
    cudaFuncSetAttribute(gemm_mma<256, 256, 1>,
                         cudaFuncAttributeMaxDynamicSharedMemorySize, SMEM);
    cudaFuncSetAttribute(gemm_mma<256, 128, 3>,
                         cudaFuncAttributeMaxDynamicSharedMemorySize, SMEM);
    cudaFuncSetAttribute(gemm_mma<384, 128, 2>,
                         cudaFuncAttributeMaxDynamicSharedMemorySize, SMEM);

    // 0. weight prep (transpose + bf16 split)
    prep_w<<<(HID * HID + 255) / 256, 256>>>(W1, (__nv_bfloat16*)w1h, (__nv_bfloat16*)w1l, HID, HID);
    prep_w<<<(HID * EMB + 255) / 256, 256>>>(W2, (__nv_bfloat16*)w2h, (__nv_bfloat16*)w2l, HID, EMB);
    prep_w<<<(3 * EMB * EMB + 255) / 256, 256>>>(Wp1, (__nv_bfloat16*)wp1h, (__nv_bfloat16*)wp1l, 3 * EMB, EMB);

    // 1. row_ptr
    build_rowptr<<<(N_NODES + 1 + 255) / 256, 256>>>(rows);
    // 2. x = fp16(node_emb + type_emb[type])
    add_emb<<<(N_NODES * HID / 4 + 255) / 256, 256>>>(node_emb, type_emb, tids);
    // 3. ax = spmm(x) -> split bf16   (fp16 gather)
    spmm_h2<HID, 1><<<N_NODES, HID / 2>>>(
        (const __half2*)pxh, nullptr, (__nv_bfloat16*)paxh, (__nv_bfloat16*)paxl,
        cols, vals, nullptr);
    // 4. h = relu(ax @ W1 + b1) -> split bf16   [HMMA]
    {
        dim3 grid((N_NODES + 127) / 128, HID / 64);
        gemm_mma<256, 256, 1><<<grid, 256, SMEM>>>(
            (const __nv_bfloat16*)paxh, (const __nv_bfloat16*)paxl,
            (const __nv_bfloat16*)w1h,  (const __nv_bfloat16*)w1l,
            nullptr, (__nv_bfloat16*)phh, (__nv_bfloat16*)phl, nullptr, b1, N_NODES);
    }
    // 5. hw = h @ W2  -> fp16   [HMMA]
    {
        dim3 grid((N_NODES + 127) / 128, EMB / 64);
        gemm_mma<256, 128, 3><<<grid, 256, SMEM>>>(
            (const __nv_bfloat16*)phh, (const __nv_bfloat16*)phl,
            (const __nv_bfloat16*)w2h, (const __nv_bfloat16*)w2l,
            nullptr, nullptr, nullptr, (__half*)phwh, nullptr, N_NODES);
    }
    // 6. z = spmm(hw) + b2   (fp16 gather, fp32 out)
    spmm_h2<EMB, 0><<<N_NODES, EMB / 2>>>(
        (const __half2*)phwh, (float*)pz, nullptr, nullptr, cols, vals, b2);
    // 7. feat (split bf16)
    build_feat<<<N_PAIRS, 3 * EMB>>>(pairs);
    // 8. hp = relu(feat @ Wp1 + bp1)  (fp32 out)   [HMMA]
    {
        dim3 grid((N_PAIRS + 127) / 128, EMB / 64);
        gemm_mma<384, 128, 2><<<grid, 256, SMEM>>>(
            (const __nv_bfloat16*)pfh,  (const __nv_bfloat16*)pfl,
            (const __nv_bfloat16*)wp1h, (const __nv_bfloat16*)wp1l,
            (float*)php, nullptr, nullptr, nullptr, bp1, N_PAIRS);
    }
    // 9. out
    final_dot<<<(N_PAIRS * 32 + 255) / 256, 256>>>(Wp2, bp2, out);
}

// round 5
// speedup vs baseline: 2.2378x; 1.2165x over previous
#include <cuda_runtime.h>
#include <cuda_fp16.h>
#include <cstdint>

#define N_NODES 100000
#define N_EDGES 3200000
#define HID 256
#define EMB 128
#define N_PAIRS 100000

// ===================== scratch (device globals) =============================
__device__ __half g_xh [N_NODES * HID];         // spmm1 input (fp16)
__device__ __half g_axh[N_NODES * HID];         // spmm1 out = GEMM1 A (fp16)
__device__ __half g_hh [N_NODES * HID];         // GEMM1 out = GEMM2 A (fp16)
__device__ __half g_hwh[N_NODES * EMB];         // GEMM2 out (fp16, feeds spmm2)
__device__ float  g_z  [N_NODES * EMB];         // spmm2 out (fp32)
__device__ __half g_feat[(size_t)N_PAIRS * 3 * EMB];   // GEMM3 A (fp16)
__device__ int    g_rowptr[N_NODES + 1];
// transposed + fp16-split weights: [N][K]
__device__ __half g_w1hi[HID * HID],      g_w1lo[HID * HID];
__device__ __half g_w2hi[EMB * HID],      g_w2lo[EMB * HID];
__device__ __half g_wp1hi[EMB * 3 * EMB], g_wp1lo[EMB * 3 * EMB];

// ===================== helpers ==============================================
__device__ __forceinline__ uint32_t smem_u32(const void* p) {
    uint32_t a;
    asm("{ .reg .u64 t; cvta.to.shared.u64 t, %1; cvt.u32.u64 %0, t; }"
        : "=r"(a) : "l"(p));
    return a;
}
__device__ __forceinline__ void cp16(uint32_t dst, const void* src) {
    asm volatile("cp.async.cg.shared.global [%0], [%1], 16;" :: "r"(dst), "l"(src));
}
#define CP_COMMIT() asm volatile("cp.async.commit_group;" ::: "memory")
#define CP_WAIT1()  asm volatile("cp.async.wait_group 1;" ::: "memory")

__device__ __forceinline__ void ldsm4(uint32_t& r0, uint32_t& r1,
                                      uint32_t& r2, uint32_t& r3, uint32_t addr) {
    asm volatile("ldmatrix.sync.aligned.m8n8.x4.shared.b16 {%0,%1,%2,%3}, [%4];"
                 : "=r"(r0), "=r"(r1), "=r"(r2), "=r"(r3) : "r"(addr));
}
__device__ __forceinline__ void mma_h(float& d0, float& d1, float& d2, float& d3,
                                      uint32_t a0, uint32_t a1, uint32_t a2, uint32_t a3,
                                      uint32_t b0, uint32_t b1) {
    asm volatile(
        "mma.sync.aligned.m16n8k16.row.col.f32.f16.f16.f32 "
        "{%0,%1,%2,%3}, {%4,%5,%6,%7}, {%8,%9}, {%0,%1,%2,%3};"
        : "+f"(d0), "+f"(d1), "+f"(d2), "+f"(d3)
        : "r"(a0), "r"(a1), "r"(a2), "r"(a3), "r"(b0), "r"(b1));
}
__device__ __forceinline__ void split_h(float v, __half& h, __half& l) {
    h = __float2half(v);
    l = __float2half(v - __half2float(h));
}

// ===================== small kernels ========================================
__global__ void build_rowptr(const int* __restrict__ rows) {
    int n = blockIdx.x * blockDim.x + threadIdx.x;
    if (n > N_NODES) return;
    int lo = 0, hi = N_EDGES;
    while (lo < hi) {
        int mid = (lo + hi) >> 1;
        if (rows[mid] < n) lo = mid + 1; else hi = mid;
    }
    g_rowptr[n] = lo;
}

// x = fp16(node_emb + type_emb[type])
__global__ void add_emb(const float* __restrict__ node_emb,
                        const float* __restrict__ type_emb,
                        const int* __restrict__ tids) {
    int i = blockIdx.x * blockDim.x + threadIdx.x;          // float4 index
    const int NV = N_NODES * HID / 4;
    if (i >= NV) return;
    int n  = i / (HID / 4);
    int k4 = i % (HID / 4);
    int t  = tids[n];
    float4 a = reinterpret_cast<const float4*>(node_emb)[i];
    float4 b = reinterpret_cast<const float4*>(type_emb)[t * (HID / 4) + k4];
    __half2 h0 = __floats2half2_rn(a.x + b.x, a.y + b.y);
    __half2 h1 = __floats2half2_rn(a.z + b.z, a.w + b.w);
    reinterpret_cast<uint2*>(g_xh)[i] =
        make_uint2(*reinterpret_cast<uint32_t*>(&h0), *reinterpret_cast<uint32_t*>(&h1));
}

// W [K,N] fp32  ->  Wt_hi/Wt_lo [N,K] fp16 split
__global__ void prep_w(const float* __restrict__ W,
                       __half* __restrict__ hi,
                       __half* __restrict__ lo, int K, int N) {
    int i = blockIdx.x * blockDim.x + threadIdx.x;
    if (i >= K * N) return;
    int k = i / N, n = i % N;
    __half h, l;
    split_h(W[i], h, l);
    hi[n * K + k] = h;
    lo[n * K + k] = l;
}

// out[p] = bp2  (pre-init for GEMM3's fused dot epilogue)
__global__ void init_out(float* __restrict__ out, const float* __restrict__ bp2) {
    int i = blockIdx.x * blockDim.x + threadIdx.x;
    if (i < N_PAIRS) out[i] = bp2[0];
}

// ---------------- SpMM (fp16 gather, fp32 accumulate) -----------------------
// One node per block, H/2 threads. OUT: 0 = fp32 (+bias), 2 = fp16.
template <int H, int OUT>
__global__ void spmm_h2(const __half2* __restrict__ x,
                        float* __restrict__ yf,
                        __half* __restrict__ yh,
                        const int* __restrict__ cols,
                        const float* __restrict__ vals,
                        const float* __restrict__ bias) {
    constexpr int H2 = H / 2;
    int n   = blockIdx.x;
    int t   = threadIdx.x;          // 0..H2-1
    int e  = g_rowptr[n];
    int e1 = g_rowptr[n + 1];
    float ax = 0.f, ay = 0.f;
    for (; e + 4 <= e1; e += 4) {
        int   c0 = __ldg(cols + e + 0), c1 = __ldg(cols + e + 1);
        int   c2 = __ldg(cols + e + 2), c3 = __ldg(cols + e + 3);
        float v0 = __ldg(vals + e + 0), v1 = __ldg(vals + e + 1);
        float v2 = __ldg(vals + e + 2), v3 = __ldg(vals + e + 3);
        float2 x0 = __half22float2(__ldg(x + (size_t)c0 * H2 + t));
        float2 x1 = __half22float2(__ldg(x + (size_t)c1 * H2 + t));
        float2 x2 = __half22float2(__ldg(x + (size_t)c2 * H2 + t));
        float2 x3 = __half22float2(__ldg(x + (size_t)c3 * H2 + t));
        ax += v0 * x0.x; ay += v0 * x0.y;
        ax += v1 * x1.x; ay += v1 * x1.y;
        ax += v2 * x2.x; ay += v2 * x2.y;
        ax += v3 * x3.x; ay += v3 * x3.y;
    }
    for (; e < e1; e++) {
        float v = __ldg(vals + e);
        float2 xv = __half22float2(__ldg(x + (size_t)__ldg(cols + e) * H2 + t));
        ax += v * xv.x; ay += v * xv.y;
    }
    if (OUT == 0) {
        if (bias) { ax += bias[2 * t]; ay += bias[2 * t + 1]; }
        *reinterpret_cast<float2*>(yf + (size_t)n * H + 2 * t) = make_float2(ax, ay);
    } else {
        __half2 p = __floats2half2_rn(ax, ay);
        *reinterpret_cast<uint32_t*>(yh + (size_t)n * H + 2 * t) =
            *reinterpret_cast<uint32_t*>(&p);
    }
}

// ===================== HMMA GEMM (fp16 A x fp16-split W, 2 products) ========
// C[M, NTOT] = A[M, KTOT] @ W^T  (A fp16; W fp16 hi/lo, shape [NTOT, KTOT])
// CTA: 128(M) x 64(N), 8 warps 4x2, warp tile 32x32, kc=32, 2-stage cp.async.
// MODE: 1 = bias+relu fp16 out; 3 = fp16 out;
//       4 = bias+relu, dot with Wp2v, atomicAdd into Cf (pre-initialized).
template <int KTOT, int NTOT, int MODE>
__global__ void __launch_bounds__(256, 2)
gemm_mma(const __half* __restrict__ Ah_,
         const __half* __restrict__ Whi,
         const __half* __restrict__ Wlo,
         float* __restrict__ Cf,
         __half* __restrict__ Ch,
         const float* __restrict__ bias,
         const float* __restrict__ Wp2v, int M) {
    constexpr int KC = 32;
    constexpr int NS = KTOT / KC;
    constexpr int ST_A  = 0;                 // 128 rows x 64B
    constexpr int ST_WH = 128 * 64;          // 8192
    constexpr int ST_WL = 128 * 64 + 64 * 64;// 12288
    constexpr int STAGE = 16384;

    extern __shared__ __align__(128) char smem[];
    const uint32_t sb = smem_u32(smem);

    const int tid  = threadIdx.x;
    const int lane = tid & 31;
    const int wm   = (tid >> 5) & 3;
    const int wn   = tid >> 7;
    const int m0   = blockIdx.x * 128;
    const int n0   = blockIdx.y * 64;

    auto load_stage = [&](int ks) {
        const int k0 = ks * KC;
        const uint32_t base = sb + (uint32_t)(ks & 1) * STAGE;
#pragma unroll
        for (int i = 0; i < 2; i++) {
            int id  = tid + i * 256;         // 0..511
            int row = id >> 2;               // 0..127
            int c   = id & 3;
            int rowg = min(m0 + row, M - 1);
            uint32_t soff = (uint32_t)(row * 64 + ((c ^ ((row >> 1) & 3)) << 4));
            cp16(base + ST_A + soff, Ah_ + (size_t)rowg * KTOT + k0 + c * 8);
        }
        {
            int row = tid >> 2;              // 0..63
            int c   = tid & 3;
            uint32_t soff = (uint32_t)(row * 64 + ((c ^ ((row >> 1) & 3)) << 4));
            size_t goff = (size_t)(n0 + row) * KTOT + k0 + c * 8;
            cp16(base + ST_WH + soff, Whi + goff);
            cp16(base + ST_WL + soff, Wlo + goff);
        }
    };

    float acc[2][4][4];
#pragma unroll
    for (int a = 0; a < 2; a++)
#pragma unroll
        for (int b = 0; b < 4; b++)
#pragma unroll
            for (int c = 0; c < 4; c++) acc[a][b][c] = 0.f;

    const int lrow  = (lane & 7) + ((lane >> 3) & 1) * 8;
    const int khalf = lane >> 4;

    load_stage(0);
    CP_COMMIT();

    for (int ks = 0; ks < NS; ks++) {
        if (ks + 1 < NS) load_stage(ks + 1);
        CP_COMMIT();
        CP_WAIT1();
        __syncthreads();

        const uint32_t base = sb + (uint32_t)(ks & 1) * STAGE;
#pragma unroll
        for (int kk = 0; kk < 2; kk++) {
            const int c = kk * 2 + khalf;
            uint32_t ah[2][4];
#pragma unroll
            for (int mi = 0; mi < 2; mi++) {
                int row = wm * 32 + mi * 16 + lrow;
                uint32_t off = (uint32_t)(row * 64 + ((c ^ ((row >> 1) & 3)) << 4));
                ldsm4(ah[mi][0], ah[mi][1], ah[mi][2], ah[mi][3], base + ST_A + off);
            }
            uint32_t bh[2][4], bl[2][4];
#pragma unroll
            for (int ng = 0; ng < 2; ng++) {
                int row = wn * 32 + ng * 16 + lrow;
                uint32_t off = (uint32_t)(row * 64 + ((c ^ ((row >> 1) & 3)) << 4));
                ldsm4(bh[ng][0], bh[ng][1], bh[ng][2], bh[ng][3], base + ST_WH + off);
                ldsm4(bl[ng][0], bl[ng][1], bl[ng][2], bl[ng][3], base + ST_WL + off);
            }
#pragma unroll
            for (int mi = 0; mi < 2; mi++)
#pragma unroll
                for (int ng = 0; ng < 2; ng++)
#pragma unroll
                    for (int sub = 0; sub < 2; sub++) {
                        int ni = ng * 2 + sub;
                        float* d = acc[mi][ni];
                        mma_h(d[0], d[1], d[2], d[3],
                              ah[mi][0], ah[mi][1], ah[mi][2], ah[mi][3],
                              bh[ng][sub], bh[ng][sub + 2]);
                        mma_h(d[0], d[1], d[2], d[3],
                              ah[mi][0], ah[mi][1], ah[mi][2], ah[mi][3],
                              bl[ng][sub], bl[ng][sub + 2]);
                    }
        }
        __syncthreads();
    }

    // ---- epilogue ----
    if (MODE == 4) {
#pragma unroll
        for (int mi = 0; mi < 2; mi++) {
            float s0 = 0.f, s1 = 0.f;
#pragma unroll
            for (int ni = 0; ni < 4; ni++) {
                int col = n0 + wn * 32 + ni * 8 + 2 * (lane & 3);
                float b0 = __ldg(bias + col),  b1 = __ldg(bias + col + 1);
                float w0 = __ldg(Wp2v + col),  w1 = __ldg(Wp2v + col + 1);
                s0 += fmaxf(acc[mi][ni][0] + b0, 0.f) * w0
                    + fmaxf(acc[mi][ni][1] + b1, 0.f) * w1;
                s1 += fmaxf(acc[mi][ni][2] + b0, 0.f) * w0
                    + fmaxf(acc[mi][ni][3] + b1, 0.f) * w1;
            }
            // reduce over the 4 lanes of the quad (same rows, different cols)
            s0 += __shfl_xor_sync(0xffffffffu, s0, 1);
            s0 += __shfl_xor_sync(0xffffffffu, s0, 2);
            s1 += __shfl_xor_sync(0xffffffffu, s1, 1);
            s1 += __shfl_xor_sync(0xffffffffu, s1, 2);
            if ((lane & 3) == 0) {
                int r0 = m0 + wm * 32 + mi * 16 + (lane >> 2);
                int r1 = r0 + 8;
                if (r0 < M) atomicAdd(Cf + r0, s0);
                if (r1 < M) atomicAdd(Cf + r1, s1);
            }
        }
        return;
    }
#pragma unroll
    for (int mi = 0; mi < 2; mi++) {
        int r0 = m0 + wm * 32 + mi * 16 + (lane >> 2);
        int r1 = r0 + 8;
#pragma unroll
        for (int ni = 0; ni < 4; ni++) {
            int col = n0 + wn * 32 + ni * 8 + 2 * (lane & 3);
            float v0 = acc[mi][ni][0], v1 = acc[mi][ni][1];
            float v2 = acc[mi][ni][2], v3 = acc[mi][ni][3];
            if (MODE == 1) {
                float b0 = __ldg(bias + col), b1 = __ldg(bias + col + 1);
                v0 = fmaxf(v0 + b0, 0.f); v1 = fmaxf(v1 + b1, 0.f);
                v2 = fmaxf(v2 + b0, 0.f); v3 = fmaxf(v3 + b1, 0.f);
            }
            if (r0 < M) {
                __half2 p = __floats2half2_rn(v0, v1);
                *reinterpret_cast<uint32_t*>(Ch + (size_t)r0 * NTOT + col) =
                    *reinterpret_cast<uint32_t*>(&p);
            }
            if (r1 < M) {
                __half2 p = __floats2half2_rn(v2, v3);
                *reinterpret_cast<uint32_t*>(Ch + (size_t)r1 * NTOT + col) =
                    *reinterpret_cast<uint32_t*>(&p);
            }
        }
    }
}

// ---------------- feat = [z[s], z[d], z[s]*z[d]] (fp16) ---------------------
__global__ void build_feat(const int* __restrict__ pairs) {
    int p = blockIdx.x;
    int j = threadIdx.x;        // 0..383
    int s = pairs[p];
    int d = pairs[N_PAIRS + p];
    float v;
    if (j < EMB)          v = g_z[s * EMB + j];
    else if (j < 2 * EMB) v = g_z[d * EMB + (j - EMB)];
    else {
        int jj = j - 2 * EMB;
        v = g_z[s * EMB + jj] * g_z[d * EMB + jj];
    }
    g_feat[(size_t)p * (3 * EMB) + j] = __float2half(v);
}

// ===========================================================================
extern "C" void kernel_launch(void* const* d_in, const int* in_sizes, int n_in,
                              void* d_out, int out_size) {
    const int*   tids     = (const int*)  d_in[0];
    const int*   rows     = (const int*)  d_in[1];
    const int*   cols     = (const int*)  d_in[2];
    const float* vals     = (const float*)d_in[3];
    const int*   pairs    = (const int*)  d_in[4];
    const float* node_emb = (const float*)d_in[5];
    const float* type_emb = (const float*)d_in[6];
    const float* W1  = (const float*)d_in[7];
    const float* b1  = (const float*)d_in[8];
    const float* W2  = (const float*)d_in[9];
    const float* b2  = (const float*)d_in[10];
    const float* Wp1 = (const float*)d_in[11];
    const float* bp1 = (const float*)d_in[12];
    const float* Wp2 = (const float*)d_in[13];
    const float* bp2 = (const float*)d_in[14];
    float* out = (float*)d_out;

    void *pxh, *paxh, *phh, *phwh, *pz, *pf;
    void *w1h, *w1l, *w2h, *w2l, *wp1h, *wp1l;
    cudaGetSymbolAddress(&pxh,  g_xh);
    cudaGetSymbolAddress(&paxh, g_axh);
    cudaGetSymbolAddress(&phh,  g_hh);
    cudaGetSymbolAddress(&phwh, g_hwh);
    cudaGetSymbolAddress(&pz,   g_z);
    cudaGetSymbolAddress(&pf,   g_feat);
    cudaGetSymbolAddress(&w1h,  g_w1hi);  cudaGetSymbolAddress(&w1l, g_w1lo);
    cudaGetSymbolAddress(&w2h,  g_w2hi);  cudaGetSymbolAddress(&w2l, g_w2lo);
    cudaGetSymbolAddress(&wp1h, g_wp1hi); cudaGetSymbolAddress(&wp1l, g_wp1lo);

    constexpr int SMEM = 2 * 16384;   // 32 KB
    cudaFuncSetAttribute(gemm_mma<256, 256, 1>,
                         cudaFuncAttributeMaxDynamicSharedMemorySize, SMEM);
    cudaFuncSetAttribute(gemm_mma<256, 128, 3>,
                         cudaFuncAttributeMaxDynamicSharedMemorySize, SMEM);
    cudaFuncSetAttribute(gemm_mma<384, 128, 4>,
                         cudaFuncAttributeMaxDynamicSharedMemorySize, SMEM);

    // 0. weight prep (transpose + fp16 split)
    prep_w<<<(HID * HID + 255) / 256, 256>>>(W1, (__half*)w1h, (__half*)w1l, HID, HID);
    prep_w<<<(HID * EMB + 255) / 256, 256>>>(W2, (__half*)w2h, (__half*)w2l, HID, EMB);
    prep_w<<<(3 * EMB * EMB + 255) / 256, 256>>>(Wp1, (__half*)wp1h, (__half*)wp1l, 3 * EMB, EMB);

    // 1. row_ptr
    build_rowptr<<<(N_NODES + 1 + 255) / 256, 256>>>(rows);
    // 2. x = fp16(node_emb + type_emb[type])
    add_emb<<<(N_NODES * HID / 4 + 255) / 256, 256>>>(node_emb, type_emb, tids);
    // 3. ax = spmm(x) -> fp16
    spmm_h2<HID, 2><<<N_NODES, HID / 2>>>(
        (const __half2*)pxh, nullptr, (__half*)paxh, cols, vals, nullptr);
    // 4. h = relu(ax @ W1 + b1) -> fp16   [HMMA]
    {
        dim3 grid((N_NODES + 127) / 128, HID / 64);
        gemm_mma<256, 256, 1><<<grid, 256, SMEM>>>(
            (const __half*)paxh, (const __half*)w1h, (const __half*)w1l,
            nullptr, (__half*)phh, b1, nullptr, N_NODES);
    }
    // 5. hw = h @ W2 -> fp16   [HMMA]
    {
        dim3 grid((N_NODES + 127) / 128, EMB / 64);
        gemm_mma<256, 128, 3><<<grid, 256, SMEM>>>(
            (const __half*)phh, (const __half*)w2h, (const __half*)w2l,
            nullptr, (__half*)phwh, nullptr, nullptr, N_NODES);
    }
    // 6. z = spmm(hw) + b2  (fp32)
    spmm_h2<EMB, 0><<<N_NODES, EMB / 2>>>(
        (const __half2*)phwh, (float*)pz, nullptr, cols, vals, b2);
    // 7. feat (fp16)
    build_feat<<<N_PAIRS, 3 * EMB>>>(pairs);
    // 8. out = relu(feat @ Wp1 + bp1) @ Wp2 + bp2   [HMMA + fused dot]
    init_out<<<(N_PAIRS + 255) / 256, 256>>>(out, bp2);
    {
        dim3 grid((N_PAIRS + 127) / 128, EMB / 64);
        gemm_mma<384, 128, 4><<<grid, 256, SMEM>>>(
            (const __half*)pf, (const __half*)wp1h, (const __half*)wp1l,
            out, nullptr, bp1, Wp2, N_PAIRS);
    }
}

// round 6
// speedup vs baseline: 2.2626x; 1.0111x over previous
#include <cuda_runtime.h>
#include <cuda_fp16.h>
#include <cstdint>

#define N_NODES 100000
#define N_EDGES 3200000
#define HID 256
#define EMB 128
#define N_PAIRS 100000

// ===================== scratch (device globals) =============================
__device__ __half g_xh [N_NODES * HID];         // spmm1 input (fp16)
__device__ __half g_axh[N_NODES * HID];         // spmm1 out = GEMM1 A (fp16)
__device__ __half g_hh [N_NODES * HID];         // GEMM1 out = GEMM2 A (fp16)
__device__ __half g_hwh[N_NODES * EMB];         // GEMM2 out (fp16, feeds spmm2)
__device__ float  g_z  [N_NODES * EMB];         // spmm2 out (fp32)
__device__ __half g_feat[(size_t)N_PAIRS * 3 * EMB];   // GEMM3 A (fp16)
__device__ int    g_rowptr[N_NODES + 1];
// transposed + fp16-split weights: [N][K]
__device__ __half g_w1hi[HID * HID],      g_w1lo[HID * HID];
__device__ __half g_w2hi[EMB * HID],      g_w2lo[EMB * HID];
__device__ __half g_wp1hi[EMB * 3 * EMB], g_wp1lo[EMB * 3 * EMB];

// ===================== helpers ==============================================
__device__ __forceinline__ uint32_t smem_u32(const void* p) {
    uint32_t a;
    asm("{ .reg .u64 t; cvta.to.shared.u64 t, %1; cvt.u32.u64 %0, t; }"
        : "=r"(a) : "l"(p));
    return a;
}
__device__ __forceinline__ void cp16(uint32_t dst, const void* src) {
    asm volatile("cp.async.cg.shared.global [%0], [%1], 16;" :: "r"(dst), "l"(src));
}
#define CP_COMMIT() asm volatile("cp.async.commit_group;" ::: "memory")
#define CP_WAIT1()  asm volatile("cp.async.wait_group 1;" ::: "memory")

__device__ __forceinline__ void ldsm4(uint32_t& r0, uint32_t& r1,
                                      uint32_t& r2, uint32_t& r3, uint32_t addr) {
    asm volatile("ldmatrix.sync.aligned.m8n8.x4.shared.b16 {%0,%1,%2,%3}, [%4];"
                 : "=r"(r0), "=r"(r1), "=r"(r2), "=r"(r3) : "r"(addr));
}
__device__ __forceinline__ void mma_h(float& d0, float& d1, float& d2, float& d3,
                                      uint32_t a0, uint32_t a1, uint32_t a2, uint32_t a3,
                                      uint32_t b0, uint32_t b1) {
    asm volatile(
        "mma.sync.aligned.m16n8k16.row.col.f32.f16.f16.f32 "
        "{%0,%1,%2,%3}, {%4,%5,%6,%7}, {%8,%9}, {%0,%1,%2,%3};"
        : "+f"(d0), "+f"(d1), "+f"(d2), "+f"(d3)
        : "r"(a0), "r"(a1), "r"(a2), "r"(a3), "r"(b0), "r"(b1));
}
__device__ __forceinline__ void split_h(float v, __half& h, __half& l) {
    h = __float2half(v);
    l = __float2half(v - __half2float(h));
}

// ===================== small kernels ========================================
__global__ void build_rowptr(const int* __restrict__ rows) {
    int n = blockIdx.x * blockDim.x + threadIdx.x;
    if (n > N_NODES) return;
    int lo = 0, hi = N_EDGES;
    while (lo < hi) {
        int mid = (lo + hi) >> 1;
        if (rows[mid] < n) lo = mid + 1; else hi = mid;
    }
    g_rowptr[n] = lo;
}

// x = fp16(node_emb + type_emb[type])
__global__ void add_emb(const float* __restrict__ node_emb,
                        const float* __restrict__ type_emb,
                        const int* __restrict__ tids) {
    int i = blockIdx.x * blockDim.x + threadIdx.x;          // float4 index
    const int NV = N_NODES * HID / 4;
    if (i >= NV) return;
    int n  = i / (HID / 4);
    int k4 = i % (HID / 4);
    int t  = tids[n];
    float4 a = reinterpret_cast<const float4*>(node_emb)[i];
    float4 b = reinterpret_cast<const float4*>(type_emb)[t * (HID / 4) + k4];
    __half2 h0 = __floats2half2_rn(a.x + b.x, a.y + b.y);
    __half2 h1 = __floats2half2_rn(a.z + b.z, a.w + b.w);
    reinterpret_cast<uint2*>(g_xh)[i] =
        make_uint2(*reinterpret_cast<uint32_t*>(&h0), *reinterpret_cast<uint32_t*>(&h1));
}

// W [K,N] fp32  ->  Wt_hi/Wt_lo [N,K] fp16 split
__global__ void prep_w(const float* __restrict__ W,
                       __half* __restrict__ hi,
                       __half* __restrict__ lo, int K, int N) {
    int i = blockIdx.x * blockDim.x + threadIdx.x;
    if (i >= K * N) return;
    int k = i / N, n = i % N;
    __half h, l;
    split_h(W[i], h, l);
    hi[n * K + k] = h;
    lo[n * K + k] = l;
}

// out[p] = bp2  (pre-init for GEMM3's fused dot epilogue)
__global__ void init_out(float* __restrict__ out, const float* __restrict__ bp2) {
    int i = blockIdx.x * blockDim.x + threadIdx.x;
    if (i < N_PAIRS) out[i] = bp2[0];
}

// ---------------- SpMM (fp16 gather, fp32 accumulate) -----------------------
// One node per block, H/2 threads. OUT: 0 = fp32 (+bias), 2 = fp16.
template <int H, int OUT>
__global__ void spmm_h2(const __half2* __restrict__ x,
                        float* __restrict__ yf,
                        __half* __restrict__ yh,
                        const int* __restrict__ cols,
                        const float* __restrict__ vals,
                        const float* __restrict__ bias) {
    constexpr int H2 = H / 2;
    int n   = blockIdx.x;
    int t   = threadIdx.x;          // 0..H2-1
    int e  = g_rowptr[n];
    int e1 = g_rowptr[n + 1];
    float ax = 0.f, ay = 0.f;
    for (; e + 4 <= e1; e += 4) {
        int   c0 = __ldg(cols + e + 0), c1 = __ldg(cols + e + 1);
        int   c2 = __ldg(cols + e + 2), c3 = __ldg(cols + e + 3);
        float v0 = __ldg(vals + e + 0), v1 = __ldg(vals + e + 1);
        float v2 = __ldg(vals + e + 2), v3 = __ldg(vals + e + 3);
        float2 x0 = __half22float2(__ldg(x + (size_t)c0 * H2 + t));
        float2 x1 = __half22float2(__ldg(x + (size_t)c1 * H2 + t));
        float2 x2 = __half22float2(__ldg(x + (size_t)c2 * H2 + t));
        float2 x3 = __half22float2(__ldg(x + (size_t)c3 * H2 + t));
        ax += v0 * x0.x; ay += v0 * x0.y;
        ax += v1 * x1.x; ay += v1 * x1.y;
        ax += v2 * x2.x; ay += v2 * x2.y;
        ax += v3 * x3.x; ay += v3 * x3.y;
    }
    for (; e < e1; e++) {
        float v = __ldg(vals + e);
        float2 xv = __half22float2(__ldg(x + (size_t)__ldg(cols + e) * H2 + t));
        ax += v * xv.x; ay += v * xv.y;
    }
    if (OUT == 0) {
        if (bias) { ax += bias[2 * t]; ay += bias[2 * t + 1]; }
        *reinterpret_cast<float2*>(yf + (size_t)n * H + 2 * t) = make_float2(ax, ay);
    } else {
        __half2 p = __floats2half2_rn(ax, ay);
        *reinterpret_cast<uint32_t*>(yh + (size_t)n * H + 2 * t) =
            *reinterpret_cast<uint32_t*>(&p);
    }
}

// ===================== HMMA GEMM (fp16 A x fp16-split W, 2 products) ========
// C[M, NTOT] = A[M, KTOT] @ W^T  (A fp16; W fp16 hi/lo, shape [NTOT, KTOT])
// CTA: 128(M) x 64(N), 8 warps 4x2, warp tile 32x32, kc=32, 2-stage cp.async.
// MODE: 1 = bias+relu fp16 out; 3 = fp16 out;
//       4 = bias+relu, dot with Wp2v, atomicAdd into Cf (pre-initialized).
template <int KTOT, int NTOT, int MODE>
__global__ void __launch_bounds__(256, 2)
gemm_mma(const __half* __restrict__ Ah_,
         const __half* __restrict__ Whi,
         const __half* __restrict__ Wlo,
         float* __restrict__ Cf,
         __half* __restrict__ Ch,
         const float* __restrict__ bias,
         const float* __restrict__ Wp2v, int M) {
    constexpr int KC = 32;
    constexpr int NS = KTOT / KC;
    constexpr int ST_A  = 0;                 // 128 rows x 64B
    constexpr int ST_WH = 128 * 64;          // 8192
    constexpr int ST_WL = 128 * 64 + 64 * 64;// 12288
    constexpr int STAGE = 16384;

    extern __shared__ __align__(128) char smem[];
    const uint32_t sb = smem_u32(smem);

    const int tid  = threadIdx.x;
    const int lane = tid & 31;
    const int wm   = (tid >> 5) & 3;
    const int wn   = tid >> 7;
    const int m0   = blockIdx.x * 128;
    const int n0   = blockIdx.y * 64;

    auto load_stage = [&](int ks) {
        const int k0 = ks * KC;
        const uint32_t base = sb + (uint32_t)(ks & 1) * STAGE;
#pragma unroll
        for (int i = 0; i < 2; i++) {
            int id  = tid + i * 256;         // 0..511
            int row = id >> 2;               // 0..127
            int c   = id & 3;
            int rowg = min(m0 + row, M - 1);
            uint32_t soff = (uint32_t)(row * 64 + ((c ^ ((row >> 1) & 3)) << 4));
            cp16(base + ST_A + soff, Ah_ + (size_t)rowg * KTOT + k0 + c * 8);
        }
        {
            int row = tid >> 2;              // 0..63
            int c   = tid & 3;
            uint32_t soff = (uint32_t)(row * 64 + ((c ^ ((row >> 1) & 3)) << 4));
            size_t goff = (size_t)(n0 + row) * KTOT + k0 + c * 8;
            cp16(base + ST_WH + soff, Whi + goff);
            cp16(base + ST_WL + soff, Wlo + goff);
        }
    };

    float acc[2][4][4];
#pragma unroll
    for (int a = 0; a < 2; a++)
#pragma unroll
        for (int b = 0; b < 4; b++)
#pragma unroll
            for (int c = 0; c < 4; c++) acc[a][b][c] = 0.f;

    const int lrow  = (lane & 7) + ((lane >> 3) & 1) * 8;
    const int khalf = lane >> 4;

    load_stage(0);
    CP_COMMIT();

    for (int ks = 0; ks < NS; ks++) {
        if (ks + 1 < NS) load_stage(ks + 1);
        CP_COMMIT();
        CP_WAIT1();
        __syncthreads();

        const uint32_t base = sb + (uint32_t)(ks & 1) * STAGE;
#pragma unroll
        for (int kk = 0; kk < 2; kk++) {
            const int c = kk * 2 + khalf;
            uint32_t ah[2][4];
#pragma unroll
            for (int mi = 0; mi < 2; mi++) {
                int row = wm * 32 + mi * 16 + lrow;
                uint32_t off = (uint32_t)(row * 64 + ((c ^ ((row >> 1) & 3)) << 4));
                ldsm4(ah[mi][0], ah[mi][1], ah[mi][2], ah[mi][3], base + ST_A + off);
            }
            uint32_t bh[2][4], bl[2][4];
#pragma unroll
            for (int ng = 0; ng < 2; ng++) {
                int row = wn * 32 + ng * 16 + lrow;
                uint32_t off = (uint32_t)(row * 64 + ((c ^ ((row >> 1) & 3)) << 4));
                ldsm4(bh[ng][0], bh[ng][1], bh[ng][2], bh[ng][3], base + ST_WH + off);
                ldsm4(bl[ng][0], bl[ng][1], bl[ng][2], bl[ng][3], base + ST_WL + off);
            }
#pragma unroll
            for (int mi = 0; mi < 2; mi++)
#pragma unroll
                for (int ng = 0; ng < 2; ng++)
#pragma unroll
                    for (int sub = 0; sub < 2; sub++) {
                        int ni = ng * 2 + sub;
                        float* d = acc[mi][ni];
                        mma_h(d[0], d[1], d[2], d[3],
                              ah[mi][0], ah[mi][1], ah[mi][2], ah[mi][3],
                              bh[ng][sub], bh[ng][sub + 2]);
                        mma_h(d[0], d[1], d[2], d[3],
                              ah[mi][0], ah[mi][1], ah[mi][2], ah[mi][3],
                              bl[ng][sub], bl[ng][sub + 2]);
                    }
        }
        __syncthreads();
    }

    // ---- epilogue ----
    if (MODE == 4) {
#pragma unroll
        for (int mi = 0; mi < 2; mi++) {
            float s0 = 0.f, s1 = 0.f;
#pragma unroll
            for (int ni = 0; ni < 4; ni++) {
                int col = n0 + wn * 32 + ni * 8 + 2 * (lane & 3);
                float b0 = __ldg(bias + col),  b1 = __ldg(bias + col + 1);
                float w0 = __ldg(Wp2v + col),  w1 = __ldg(Wp2v + col + 1);
                s0 += fmaxf(acc[mi][ni][0] + b0, 0.f) * w0
                    + fmaxf(acc[mi][ni][1] + b1, 0.f) * w1;
                s1 += fmaxf(acc[mi][ni][2] + b0, 0.f) * w0
                    + fmaxf(acc[mi][ni][3] + b1, 0.f) * w1;
            }
            // reduce over the 4 lanes of the quad (same rows, different cols)
            s0 += __shfl_xor_sync(0xffffffffu, s0, 1);
            s0 += __shfl_xor_sync(0xffffffffu, s0, 2);
            s1 += __shfl_xor_sync(0xffffffffu, s1, 1);
            s1 += __shfl_xor_sync(0xffffffffu, s1, 2);
            if ((lane & 3) == 0) {
                int r0 = m0 + wm * 32 + mi * 16 + (lane >> 2);
                int r1 = r0 + 8;
                if (r0 < M) atomicAdd(Cf + r0, s0);
                if (r1 < M) atomicAdd(Cf + r1, s1);
            }
        }
        return;
    }
#pragma unroll
    for (int mi = 0; mi < 2; mi++) {
        int r0 = m0 + wm * 32 + mi * 16 + (lane >> 2);
        int r1 = r0 + 8;
#pragma unroll
        for (int ni = 0; ni < 4; ni++) {
            int col = n0 + wn * 32 + ni * 8 + 2 * (lane & 3);
            float v0 = acc[mi][ni][0], v1 = acc[mi][ni][1];
            float v2 = acc[mi][ni][2], v3 = acc[mi][ni][3];
            if (MODE == 1) {
                float b0 = __ldg(bias + col), b1 = __ldg(bias + col + 1);
                v0 = fmaxf(v0 + b0, 0.f); v1 = fmaxf(v1 + b1, 0.f);
                v2 = fmaxf(v2 + b0, 0.f); v3 = fmaxf(v3 + b1, 0.f);
            }
            if (r0 < M) {
                __half2 p = __floats2half2_rn(v0, v1);
                *reinterpret_cast<uint32_t*>(Ch + (size_t)r0 * NTOT + col) =
                    *reinterpret_cast<uint32_t*>(&p);
            }
            if (r1 < M) {
                __half2 p = __floats2half2_rn(v2, v3);
                *reinterpret_cast<uint32_t*>(Ch + (size_t)r1 * NTOT + col) =
                    *reinterpret_cast<uint32_t*>(&p);
            }
        }
    }
}

// ---------------- feat = [z[s], z[d], z[s]*z[d]] (fp16) ---------------------
__global__ void build_feat(const int* __restrict__ pairs) {
    int p = blockIdx.x;
    int j = threadIdx.x;        // 0..383
    int s = pairs[p];
    int d = pairs[N_PAIRS + p];
    float v;
    if (j < EMB)          v = g_z[s * EMB + j];
    else if (j < 2 * EMB) v = g_z[d * EMB + (j - EMB)];
    else {
        int jj = j - 2 * EMB;
        v = g_z[s * EMB + jj] * g_z[d * EMB + jj];
    }
    g_feat[(size_t)p * (3 * EMB) + j] = __float2half(v);
}

// ===========================================================================
extern "C" void kernel_launch(void* const* d_in, const int* in_sizes, int n_in,
                              void* d_out, int out_size) {
    const int*   tids     = (const int*)  d_in[0];
    const int*   rows     = (const int*)  d_in[1];
    const int*   cols     = (const int*)  d_in[2];
    const float* vals     = (const float*)d_in[3];
    const int*   pairs    = (const int*)  d_in[4];
    const float* node_emb = (const float*)d_in[5];
    const float* type_emb = (const float*)d_in[6];
    const float* W1  = (const float*)d_in[7];
    const float* b1  = (const float*)d_in[8];
    const float* W2  = (const float*)d_in[9];
    const float* b2  = (const float*)d_in[10];
    const float* Wp1 = (const float*)d_in[11];
    const float* bp1 = (const float*)d_in[12];
    const float* Wp2 = (const float*)d_in[13];
    const float* bp2 = (const float*)d_in[14];
    float* out = (float*)d_out;

    void *pxh, *paxh, *phh, *phwh, *pz, *pf;
    void *w1h, *w1l, *w2h, *w2l, *wp1h, *wp1l;
    cudaGetSymbolAddress(&pxh,  g_xh);
    cudaGetSymbolAddress(&paxh, g_axh);
    cudaGetSymbolAddress(&phh,  g_hh);
    cudaGetSymbolAddress(&phwh, g_hwh);
    cudaGetSymbolAddress(&pz,   g_z);
    cudaGetSymbolAddress(&pf,   g_feat);
    cudaGetSymbolAddress(&w1h,  g_w1hi);  cudaGetSymbolAddress(&w1l, g_w1lo);
    cudaGetSymbolAddress(&w2h,  g_w2hi);  cudaGetSymbolAddress(&w2l, g_w2lo);
    cudaGetSymbolAddress(&wp1h, g_wp1hi); cudaGetSymbolAddress(&wp1l, g_wp1lo);

    constexpr int SMEM = 2 * 16384;   // 32 KB
    cudaFuncSetAttribute(gemm_mma<256, 256, 1>,
                         cudaFuncAttributeMaxDynamicSharedMemorySize, SMEM);
    cudaFuncSetAttribute(gemm_mma<256, 128, 3>,
                         cudaFuncAttributeMaxDynamicSharedMemorySize, SMEM);
    cudaFuncSetAttribute(gemm_mma<384, 128, 4>,
                         cudaFuncAttributeMaxDynamicSharedMemorySize, SMEM);

    // 0. weight prep (transpose + fp16 split)
    prep_w<<<(HID * HID + 255) / 256, 256>>>(W1, (__half*)w1h, (__half*)w1l, HID, HID);
    prep_w<<<(HID * EMB + 255) / 256, 256>>>(W2, (__half*)w2h, (__half*)w2l, HID, EMB);
    prep_w<<<(3 * EMB * EMB + 255) / 256, 256>>>(Wp1, (__half*)wp1h, (__half*)wp1l, 3 * EMB, EMB);

    // 1. row_ptr
    build_rowptr<<<(N_NODES + 1 + 255) / 256, 256>>>(rows);
    // 2. x = fp16(node_emb + type_emb[type])
    add_emb<<<(N_NODES * HID / 4 + 255) / 256, 256>>>(node_emb, type_emb, tids);
    // 3. ax = spmm(x) -> fp16
    spmm_h2<HID, 2><<<N_NODES, HID / 2>>>(
        (const __half2*)pxh, nullptr, (__half*)paxh, cols, vals, nullptr);
    // 4. h = relu(ax @ W1 + b1) -> fp16   [HMMA]
    {
        dim3 grid((N_NODES + 127) / 128, HID / 64);
        gemm_mma<256, 256, 1><<<grid, 256, SMEM>>>(
            (const __half*)paxh, (const __half*)w1h, (const __half*)w1l,
            nullptr, (__half*)phh, b1, nullptr, N_NODES);
    }
    // 5. hw = h @ W2 -> fp16   [HMMA]
    {
        dim3 grid((N_NODES + 127) / 128, EMB / 64);
        gemm_mma<256, 128, 3><<<grid, 256, SMEM>>>(
            (const __half*)phh, (const __half*)w2h, (const __half*)w2l,
            nullptr, (__half*)phwh, nullptr, nullptr, N_NODES);
    }
    // 6. z = spmm(hw) + b2  (fp32)
    spmm_h2<EMB, 0><<<N_NODES, EMB / 2>>>(
        (const __half2*)phwh, (float*)pz, nullptr, cols, vals, b2);
    // 7. feat (fp16)
    build_feat<<<N_PAIRS, 3 * EMB>>>(pairs);
    // 8. out = relu(feat @ Wp1 + bp1) @ Wp2 + bp2   [HMMA + fused dot]
    init_out<<<(N_PAIRS + 255) / 256, 256>>>(out, bp2);
    {
        dim3 grid((N_PAIRS + 127) / 128, EMB / 64);
        gemm_mma<384, 128, 4><<<grid, 256, SMEM>>>(
            (const __half*)pf, (const __half*)wp1h, (const __half*)wp1l,
            out, nullptr, bp1, Wp2, N_PAIRS);
    }
}

// round 7
// speedup vs baseline: 2.2897x; 1.0120x over previous
#include <cuda_runtime.h>
#include <cuda_fp16.h>
#include <cstdint>

#define N_NODES 100000
#define N_EDGES 3200000
#define HID 256
#define EMB 128
#define N_PAIRS 100000

// ===================== scratch (device globals) =============================
__device__ __half g_xh [N_NODES * HID];         // spmm1 input (fp16)
__device__ __half g_axh[N_NODES * HID];         // spmm1 out = GEMM1 A (fp16)
__device__ __half g_hh [N_NODES * HID];         // GEMM1 out = GEMM2 A (fp16)
__device__ __half g_hwh[N_NODES * EMB];         // GEMM2 out (fp16, feeds spmm2)
__device__ float  g_z  [N_NODES * EMB];         // spmm2 out (fp32)
__device__ __half g_feat[(size_t)N_PAIRS * 3 * EMB];   // GEMM3 A (fp16)
__device__ int    g_rowptr[N_NODES + 1];
// transposed + fp16-split weights: [N][K]
__device__ __half g_w1hi[HID * HID],      g_w1lo[HID * HID];
__device__ __half g_w2hi[EMB * HID],      g_w2lo[EMB * HID];
__device__ __half g_wp1hi[EMB * 3 * EMB], g_wp1lo[EMB * 3 * EMB];

// ===================== helpers ==============================================
__device__ __forceinline__ uint32_t smem_u32(const void* p) {
    uint32_t a;
    asm("{ .reg .u64 t; cvta.to.shared.u64 t, %1; cvt.u32.u64 %0, t; }"
        : "=r"(a) : "l"(p));
    return a;
}
__device__ __forceinline__ void cp16(uint32_t dst, const void* src) {
    asm volatile("cp.async.cg.shared.global [%0], [%1], 16;" :: "r"(dst), "l"(src));
}
#define CP_COMMIT() asm volatile("cp.async.commit_group;" ::: "memory")
#define CP_WAIT1()  asm volatile("cp.async.wait_group 1;" ::: "memory")

__device__ __forceinline__ void ldsm4(uint32_t& r0, uint32_t& r1,
                                      uint32_t& r2, uint32_t& r3, uint32_t addr) {
    asm volatile("ldmatrix.sync.aligned.m8n8.x4.shared.b16 {%0,%1,%2,%3}, [%4];"
                 : "=r"(r0), "=r"(r1), "=r"(r2), "=r"(r3) : "r"(addr));
}
__device__ __forceinline__ void mma_h(float& d0, float& d1, float& d2, float& d3,
                                      uint32_t a0, uint32_t a1, uint32_t a2, uint32_t a3,
                                      uint32_t b0, uint32_t b1) {
    asm volatile(
        "mma.sync.aligned.m16n8k16.row.col.f32.f16.f16.f32 "
        "{%0,%1,%2,%3}, {%4,%5,%6,%7}, {%8,%9}, {%0,%1,%2,%3};"
        : "+f"(d0), "+f"(d1), "+f"(d2), "+f"(d3)
        : "r"(a0), "r"(a1), "r"(a2), "r"(a3), "r"(b0), "r"(b1));
}
__device__ __forceinline__ void split_h(float v, __half& h, __half& l) {
    h = __float2half(v);
    l = __float2half(v - __half2float(h));
}

// ===================== small kernels ========================================
// rowptr via edge-boundary scatter (rows sorted ascending)
__global__ void build_rowptr(const int* __restrict__ rows) {
    int e = blockIdx.x * blockDim.x + threadIdx.x;
    if (e >= N_EDGES) return;
    int r  = rows[e];
    int rn = (e + 1 < N_EDGES) ? rows[e + 1] : N_NODES;
    if (e == 0)
        for (int n = 0; n <= r; n++) g_rowptr[n] = 0;
    for (int n = r + 1; n <= rn; n++) g_rowptr[n] = e + 1;
}

// x = fp16(node_emb + type_emb[type])
__global__ void add_emb(const float* __restrict__ node_emb,
                        const float* __restrict__ type_emb,
                        const int* __restrict__ tids) {
    int i = blockIdx.x * blockDim.x + threadIdx.x;          // float4 index
    const int NV = N_NODES * HID / 4;
    if (i >= NV) return;
    int n  = i / (HID / 4);
    int k4 = i % (HID / 4);
    int t  = tids[n];
    float4 a = reinterpret_cast<const float4*>(node_emb)[i];
    float4 b = reinterpret_cast<const float4*>(type_emb)[t * (HID / 4) + k4];
    __half2 h0 = __floats2half2_rn(a.x + b.x, a.y + b.y);
    __half2 h1 = __floats2half2_rn(a.z + b.z, a.w + b.w);
    reinterpret_cast<uint2*>(g_xh)[i] =
        make_uint2(*reinterpret_cast<uint32_t*>(&h0), *reinterpret_cast<uint32_t*>(&h1));
}

// W [K,N] fp32  ->  Wt_hi/Wt_lo [N,K] fp16 split
__global__ void prep_w(const float* __restrict__ W,
                       __half* __restrict__ hi,
                       __half* __restrict__ lo, int K, int N) {
    int i = blockIdx.x * blockDim.x + threadIdx.x;
    if (i >= K * N) return;
    int k = i / N, n = i % N;
    __half h, l;
    split_h(W[i], h, l);
    hi[n * K + k] = h;
    lo[n * K + k] = l;
}

// out[p] = bp2  (pre-init for GEMM3's fused dot epilogue)
__global__ void init_out(float* __restrict__ out, const float* __restrict__ bp2) {
    int i = blockIdx.x * blockDim.x + threadIdx.x;
    if (i < N_PAIRS) out[i] = bp2[0];
}

// ---------------- SpMM (fp16 gather, fp32 accumulate) -----------------------
// One node per block, H/2 threads. OUT: 0 = fp32 (+bias), 2 = fp16.
template <int H, int OUT>
__global__ void spmm_h2(const __half2* __restrict__ x,
                        float* __restrict__ yf,
                        __half* __restrict__ yh,
                        const int* __restrict__ cols,
                        const float* __restrict__ vals,
                        const float* __restrict__ bias) {
    constexpr int H2 = H / 2;
    int n   = blockIdx.x;
    int t   = threadIdx.x;          // 0..H2-1
    int e  = g_rowptr[n];
    int e1 = g_rowptr[n + 1];
    float ax = 0.f, ay = 0.f;
    for (; e + 8 <= e1; e += 8) {
        int c[8]; float v[8];
#pragma unroll
        for (int j = 0; j < 8; j++) {
            c[j] = __ldg(cols + e + j);
            v[j] = __ldg(vals + e + j);
        }
#pragma unroll
        for (int j = 0; j < 8; j++) {
            float2 xv = __half22float2(__ldg(x + (size_t)c[j] * H2 + t));
            ax += v[j] * xv.x; ay += v[j] * xv.y;
        }
    }
    if (e + 4 <= e1) {
        int c[4]; float v[4];
#pragma unroll
        for (int j = 0; j < 4; j++) {
            c[j] = __ldg(cols + e + j);
            v[j] = __ldg(vals + e + j);
        }
#pragma unroll
        for (int j = 0; j < 4; j++) {
            float2 xv = __half22float2(__ldg(x + (size_t)c[j] * H2 + t));
            ax += v[j] * xv.x; ay += v[j] * xv.y;
        }
        e += 4;
    }
    for (; e < e1; e++) {
        float v = __ldg(vals + e);
        float2 xv = __half22float2(__ldg(x + (size_t)__ldg(cols + e) * H2 + t));
        ax += v * xv.x; ay += v * xv.y;
    }
    if (OUT == 0) {
        if (bias) { ax += bias[2 * t]; ay += bias[2 * t + 1]; }
        *reinterpret_cast<float2*>(yf + (size_t)n * H + 2 * t) = make_float2(ax, ay);
    } else {
        __half2 p = __floats2half2_rn(ax, ay);
        *reinterpret_cast<uint32_t*>(yh + (size_t)n * H + 2 * t) =
            *reinterpret_cast<uint32_t*>(&p);
    }
}

// ===================== HMMA GEMM (fp16 A x fp16-split W, 2 products) ========
// C[M, NTOT] = A[M, KTOT] @ W^T  (A fp16; W fp16 hi/lo, shape [NTOT, KTOT])
// CTA tile 128(M) x 128(N), 8 warps in 4(M) x 2(N), warp tile 32x64,
// kc=32, 2-stage cp.async.
// MODE: 1 = bias+relu fp16 out; 3 = fp16 out;
//       4 = bias+relu, dot with Wp2v, atomicAdd into Cf (pre-initialized).
template <int KTOT, int NTOT, int MODE>
__global__ void __launch_bounds__(256, 2)
gemm_mma(const __half* __restrict__ Ah_,
         const __half* __restrict__ Whi,
         const __half* __restrict__ Wlo,
         float* __restrict__ Cf,
         __half* __restrict__ Ch,
         const float* __restrict__ bias,
         const float* __restrict__ Wp2v, int M) {
    constexpr int KC = 32;
    constexpr int NS = KTOT / KC;
    constexpr int ST_A  = 0;                   // 128 rows x 64B = 8KB
    constexpr int ST_WH = 8192;                // 128 rows x 64B = 8KB
    constexpr int ST_WL = 16384;               // 8KB
    constexpr int STAGE = 24576;

    extern __shared__ __align__(128) char smem[];
    const uint32_t sb = smem_u32(smem);

    const int tid  = threadIdx.x;
    const int lane = tid & 31;
    const int wm   = (tid >> 5) & 3;           // 4 M groups of 32 rows
    const int wn   = tid >> 7;                 // 2 N groups of 64 cols
    const int m0   = blockIdx.x * 128;
    const int n0   = blockIdx.y * 128;

    auto load_stage = [&](int ks) {
        const int k0 = ks * KC;
        const uint32_t base = sb + (uint32_t)(ks & 1) * STAGE;
#pragma unroll
        for (int i = 0; i < 2; i++) {
            int id  = tid + i * 256;           // 0..511
            int row = id >> 2;                 // 0..127
            int c   = id & 3;
            uint32_t soff = (uint32_t)(row * 64 + ((c ^ ((row >> 1) & 3)) << 4));
            int rowa = min(m0 + row, M - 1);
            cp16(base + ST_A + soff, Ah_ + (size_t)rowa * KTOT + k0 + c * 8);
            size_t goff = (size_t)(n0 + row) * KTOT + k0 + c * 8;
            cp16(base + ST_WH + soff, Whi + goff);
            cp16(base + ST_WL + soff, Wlo + goff);
        }
    };

    float acc[2][8][4];
#pragma unroll
    for (int a = 0; a < 2; a++)
#pragma unroll
        for (int b = 0; b < 8; b++)
#pragma unroll
            for (int c = 0; c < 4; c++) acc[a][b][c] = 0.f;

    const int lrow  = (lane & 7) + ((lane >> 3) & 1) * 8;
    const int khalf = lane >> 4;

    load_stage(0);
    CP_COMMIT();

    for (int ks = 0; ks < NS; ks++) {
        if (ks + 1 < NS) load_stage(ks + 1);
        CP_COMMIT();
        CP_WAIT1();
        __syncthreads();

        const uint32_t base = sb + (uint32_t)(ks & 1) * STAGE;
#pragma unroll
        for (int kk = 0; kk < 2; kk++) {
            const int c = kk * 2 + khalf;
            uint32_t ah[2][4];
#pragma unroll
            for (int mi = 0; mi < 2; mi++) {
                int row = wm * 32 + mi * 16 + lrow;
                uint32_t off = (uint32_t)(row * 64 + ((c ^ ((row >> 1) & 3)) << 4));
                ldsm4(ah[mi][0], ah[mi][1], ah[mi][2], ah[mi][3], base + ST_A + off);
            }
            uint32_t bh[4][4], bl[4][4];
#pragma unroll
            for (int ng = 0; ng < 4; ng++) {
                int row = wn * 64 + ng * 16 + lrow;
                uint32_t off = (uint32_t)(row * 64 + ((c ^ ((row >> 1) & 3)) << 4));
                ldsm4(bh[ng][0], bh[ng][1], bh[ng][2], bh[ng][3], base + ST_WH + off);
                ldsm4(bl[ng][0], bl[ng][1], bl[ng][2], bl[ng][3], base + ST_WL + off);
            }
#pragma unroll
            for (int mi = 0; mi < 2; mi++)
#pragma unroll
                for (int ng = 0; ng < 4; ng++)
#pragma unroll
                    for (int sub = 0; sub < 2; sub++) {
                        int ni = ng * 2 + sub;
                        float* d = acc[mi][ni];
                        mma_h(d[0], d[1], d[2], d[3],
                              ah[mi][0], ah[mi][1], ah[mi][2], ah[mi][3],
                              bh[ng][sub], bh[ng][sub + 2]);
                        mma_h(d[0], d[1], d[2], d[3],
                              ah[mi][0], ah[mi][1], ah[mi][2], ah[mi][3],
                              bl[ng][sub], bl[ng][sub + 2]);
                    }
        }
        __syncthreads();
    }

    // ---- epilogue ----
    if (MODE == 4) {
#pragma unroll
        for (int mi = 0; mi < 2; mi++) {
            float s0 = 0.f, s1 = 0.f;
#pragma unroll
            for (int ni = 0; ni < 8; ni++) {
                int col = n0 + wn * 64 + ni * 8 + 2 * (lane & 3);
                float b0 = __ldg(bias + col),  b1 = __ldg(bias + col + 1);
                float w0 = __ldg(Wp2v + col),  w1 = __ldg(Wp2v + col + 1);
                s0 += fmaxf(acc[mi][ni][0] + b0, 0.f) * w0
                    + fmaxf(acc[mi][ni][1] + b1, 0.f) * w1;
                s1 += fmaxf(acc[mi][ni][2] + b0, 0.f) * w0
                    + fmaxf(acc[mi][ni][3] + b1, 0.f) * w1;
            }
            s0 += __shfl_xor_sync(0xffffffffu, s0, 1);
            s0 += __shfl_xor_sync(0xffffffffu, s0, 2);
            s1 += __shfl_xor_sync(0xffffffffu, s1, 1);
            s1 += __shfl_xor_sync(0xffffffffu, s1, 2);
            if ((lane & 3) == 0) {
                int r0 = m0 + wm * 32 + mi * 16 + (lane >> 2);
                int r1 = r0 + 8;
                if (r0 < M) atomicAdd(Cf + r0, s0);
                if (r1 < M) atomicAdd(Cf + r1, s1);
            }
        }
        return;
    }
#pragma unroll
    for (int mi = 0; mi < 2; mi++) {
        int r0 = m0 + wm * 32 + mi * 16 + (lane >> 2);
        int r1 = r0 + 8;
#pragma unroll
        for (int ni = 0; ni < 8; ni++) {
            int col = n0 + wn * 64 + ni * 8 + 2 * (lane & 3);
            float v0 = acc[mi][ni][0], v1 = acc[mi][ni][1];
            float v2 = acc[mi][ni][2], v3 = acc[mi][ni][3];
            if (MODE == 1) {
                float b0 = __ldg(bias + col), b1 = __ldg(bias + col + 1);
                v0 = fmaxf(v0 + b0, 0.f); v1 = fmaxf(v1 + b1, 0.f);
                v2 = fmaxf(v2 + b0, 0.f); v3 = fmaxf(v3 + b1, 0.f);
            }
            if (r0 < M) {
                __half2 p = __floats2half2_rn(v0, v1);
                *reinterpret_cast<uint32_t*>(Ch + (size_t)r0 * NTOT + col) =
                    *reinterpret_cast<uint32_t*>(&p);
            }
            if (r1 < M) {
                __half2 p = __floats2half2_rn(v2, v3);
                *reinterpret_cast<uint32_t*>(Ch + (size_t)r1 * NTOT + col) =
                    *reinterpret_cast<uint32_t*>(&p);
            }
        }
    }
}

// ---------------- feat = [z[s], z[d], z[s]*z[d]] (fp16) ---------------------
__global__ void build_feat(const int* __restrict__ pairs) {
    int p = blockIdx.x;
    int j = threadIdx.x;        // 0..383
    int s = pairs[p];
    int d = pairs[N_PAIRS + p];
    float v;
    if (j < EMB)          v = g_z[s * EMB + j];
    else if (j < 2 * EMB) v = g_z[d * EMB + (j - EMB)];
    else {
        int jj = j - 2 * EMB;
        v = g_z[s * EMB + jj] * g_z[d * EMB + jj];
    }
    g_feat[(size_t)p * (3 * EMB) + j] = __float2half(v);
}

// ===========================================================================
extern "C" void kernel_launch(void* const* d_in, const int* in_sizes, int n_in,
                              void* d_out, int out_size) {
    const int*   tids     = (const int*)  d_in[0];
    const int*   rows     = (const int*)  d_in[1];
    const int*   cols     = (const int*)  d_in[2];
    const float* vals     = (const float*)d_in[3];
    const int*   pairs    = (const int*)  d_in[4];
    const float* node_emb = (const float*)d_in[5];
    const float* type_emb = (const float*)d_in[6];
    const float* W1  = (const float*)d_in[7];
    const float* b1  = (const float*)d_in[8];
    const float* W2  = (const float*)d_in[9];
    const float* b2  = (const float*)d_in[10];
    const float* Wp1 = (const float*)d_in[11];
    const float* bp1 = (const float*)d_in[12];
    const float* Wp2 = (const float*)d_in[13];
    const float* bp2 = (const float*)d_in[14];
    float* out = (float*)d_out;

    void *pxh, *paxh, *phh, *phwh, *pz, *pf;
    void *w1h, *w1l, *w2h, *w2l, *wp1h, *wp1l;
    cudaGetSymbolAddress(&pxh,  g_xh);
    cudaGetSymbolAddress(&paxh, g_axh);
    cudaGetSymbolAddress(&phh,  g_hh);
    cudaGetSymbolAddress(&phwh, g_hwh);
    cudaGetSymbolAddress(&pz,   g_z);
    cudaGetSymbolAddress(&pf,   g_feat);
    cudaGetSymbolAddress(&w1h,  g_w1hi);  cudaGetSymbolAddress(&w1l, g_w1lo);
    cudaGetSymbolAddress(&w2h,  g_w2hi);  cudaGetSymbolAddress(&w2l, g_w2lo);
    cudaGetSymbolAddress(&wp1h, g_wp1hi); cudaGetSymbolAddress(&wp1l, g_wp1lo);

    constexpr int SMEM = 2 * 24576;   // 48 KB
    cudaFuncSetAttribute(gemm_mma<256, 256, 1>,
                         cudaFuncAttributeMaxDynamicSharedMemorySize, SMEM);
    cudaFuncSetAttribute(gemm_mma<256, 128, 3>,
                         cudaFuncAttributeMaxDynamicSharedMemorySize, SMEM);
    cudaFuncSetAttribute(gemm_mma<384, 128, 4>,
                         cudaFuncAttributeMaxDynamicSharedMemorySize, SMEM);

    // 0. weight prep (transpose + fp16 split)
    prep_w<<<(HID * HID + 255) / 256, 256>>>(W1, (__half*)w1h, (__half*)w1l, HID, HID);
    prep_w<<<(HID * EMB + 255) / 256, 256>>>(W2, (__half*)w2h, (__half*)w2l, HID, EMB);
    prep_w<<<(3 * EMB * EMB + 255) / 256, 256>>>(Wp1, (__half*)wp1h, (__half*)wp1l, 3 * EMB, EMB);

    // 1. row_ptr (edge-boundary scatter)
    build_rowptr<<<(N_EDGES + 255) / 256, 256>>>(rows);
    // 2. x = fp16(node_emb + type_emb[type])
    add_emb<<<(N_NODES * HID / 4 + 255) / 256, 256>>>(node_emb, type_emb, tids);
    // 3. ax = spmm(x) -> fp16
    spmm_h2<HID, 2><<<N_NODES, HID / 2>>>(
        (const __half2*)pxh, nullptr, (__half*)paxh, cols, vals, nullptr);
    // 4. h = relu(ax @ W1 + b1) -> fp16   [HMMA 128x128]
    {
        dim3 grid((N_NODES + 127) / 128, HID / 128);
        gemm_mma<256, 256, 1><<<grid, 256, SMEM>>>(
            (const __half*)paxh, (const __half*)w1h, (const __half*)w1l,
            nullptr, (__half*)phh, b1, nullptr, N_NODES);
    }
    // 5. hw = h @ W2 -> fp16   [HMMA 128x128]
    {
        dim3 grid((N_NODES + 127) / 128, EMB / 128);
        gemm_mma<256, 128, 3><<<grid, 256, SMEM>>>(
            (const __half*)phh, (const __half*)w2h, (const __half*)w2l,
            nullptr, (__half*)phwh, nullptr, nullptr, N_NODES);
    }
    // 6. z = spmm(hw) + b2  (fp32)
    spmm_h2<EMB, 0><<<N_NODES, EMB / 2>>>(
        (const __half2*)phwh, (float*)pz, nullptr, cols, vals, b2);
    // 7. feat (fp16)
    build_feat<<<N_PAIRS, 3 * EMB>>>(pairs);
    // 8. out = relu(feat @ Wp1 + bp1) @ Wp2 + bp2   [HMMA 128x128 + fused dot]
    init_out<<<(N_PAIRS + 255) / 256, 256>>>(out, bp2);
    {
        dim3 grid((N_PAIRS + 127) / 128, EMB / 128);
        gemm_mma<384, 128, 4><<<grid, 256, SMEM>>>(
            (const __half*)pf, (const __half*)wp1h, (const __half*)wp1l,
            out, nullptr, bp1, Wp2, N_PAIRS);
    }
}

// round 8
// speedup vs baseline: 2.6851x; 1.1727x over previous
#include <cuda_runtime.h>
#include <cuda_fp16.h>
#include <cstdint>

#define N_NODES 100000
#define N_EDGES 3200000
#define HID 256
#define EMB 128
#define N_PAIRS 100000

// ===================== scratch (device globals) =============================
__device__ __half g_xh [N_NODES * HID];         // spmm1 input (fp16)
__device__ __half g_axh[N_NODES * HID];         // spmm1 out = GEMM1 A (fp16)
__device__ __half g_hh [N_NODES * HID];         // GEMM1 out = GEMM2 A (fp16)
__device__ __half g_hwh[N_NODES * EMB];         // GEMM2 out (fp16, feeds spmm2)
__device__ float  g_z  [N_NODES * EMB];         // spmm2 out (fp32)
__device__ __half g_feat[(size_t)N_PAIRS * 3 * EMB];   // GEMM3 A (fp16)
__device__ int    g_rowptr[N_NODES + 1];
// transposed + fp16-split weights: [N][K]
__device__ __half g_w1hi[HID * HID],      g_w1lo[HID * HID];
__device__ __half g_w2hi[EMB * HID],      g_w2lo[EMB * HID];
__device__ __half g_wp1hi[EMB * 3 * EMB], g_wp1lo[EMB * 3 * EMB];

// ===================== helpers ==============================================
__device__ __forceinline__ uint32_t smem_u32(const void* p) {
    uint32_t a;
    asm("{ .reg .u64 t; cvta.to.shared.u64 t, %1; cvt.u32.u64 %0, t; }"
        : "=r"(a) : "l"(p));
    return a;
}
__device__ __forceinline__ void cp16(uint32_t dst, const void* src) {
    asm volatile("cp.async.cg.shared.global [%0], [%1], 16;" :: "r"(dst), "l"(src));
}
#define CP_COMMIT() asm volatile("cp.async.commit_group;" ::: "memory")
#define CP_WAIT1()  asm volatile("cp.async.wait_group 1;" ::: "memory")

__device__ __forceinline__ void ldsm4(uint32_t& r0, uint32_t& r1,
                                      uint32_t& r2, uint32_t& r3, uint32_t addr) {
    asm volatile("ldmatrix.sync.aligned.m8n8.x4.shared.b16 {%0,%1,%2,%3}, [%4];"
                 : "=r"(r0), "=r"(r1), "=r"(r2), "=r"(r3) : "r"(addr));
}
__device__ __forceinline__ void mma_h(float& d0, float& d1, float& d2, float& d3,
                                      uint32_t a0, uint32_t a1, uint32_t a2, uint32_t a3,
                                      uint32_t b0, uint32_t b1) {
    asm volatile(
        "mma.sync.aligned.m16n8k16.row.col.f32.f16.f16.f32 "
        "{%0,%1,%2,%3}, {%4,%5,%6,%7}, {%8,%9}, {%0,%1,%2,%3};"
        : "+f"(d0), "+f"(d1), "+f"(d2), "+f"(d3)
        : "r"(a0), "r"(a1), "r"(a2), "r"(a3), "r"(b0), "r"(b1));
}
__device__ __forceinline__ void split_h(float v, __half& h, __half& l) {
    h = __float2half(v);
    l = __float2half(v - __half2float(h));
}
__device__ __forceinline__ float2 h2f2(uint32_t u) {
    return __half22float2(*reinterpret_cast<__half2*>(&u));
}

// ===================== small kernels ========================================
// rowptr via edge-boundary scatter (rows sorted ascending)
__global__ void build_rowptr(const int* __restrict__ rows) {
    int e = blockIdx.x * blockDim.x + threadIdx.x;
    if (e >= N_EDGES) return;
    int r  = rows[e];
    int rn = (e + 1 < N_EDGES) ? rows[e + 1] : N_NODES;
    if (e == 0)
        for (int n = 0; n <= r; n++) g_rowptr[n] = 0;
    for (int n = r + 1; n <= rn; n++) g_rowptr[n] = e + 1;
}

// x = fp16(node_emb + type_emb[type])
__global__ void add_emb(const float* __restrict__ node_emb,
                        const float* __restrict__ type_emb,
                        const int* __restrict__ tids) {
    int i = blockIdx.x * blockDim.x + threadIdx.x;          // float4 index
    const int NV = N_NODES * HID / 4;
    if (i >= NV) return;
    int n  = i / (HID / 4);
    int k4 = i % (HID / 4);
    int t  = tids[n];
    float4 a = reinterpret_cast<const float4*>(node_emb)[i];
    float4 b = reinterpret_cast<const float4*>(type_emb)[t * (HID / 4) + k4];
    __half2 h0 = __floats2half2_rn(a.x + b.x, a.y + b.y);
    __half2 h1 = __floats2half2_rn(a.z + b.z, a.w + b.w);
    reinterpret_cast<uint2*>(g_xh)[i] =
        make_uint2(*reinterpret_cast<uint32_t*>(&h0), *reinterpret_cast<uint32_t*>(&h1));
}

// W [K,N] fp32  ->  Wt_hi/Wt_lo [N,K] fp16 split
__global__ void prep_w(const float* __restrict__ W,
                       __half* __restrict__ hi,
                       __half* __restrict__ lo, int K, int N) {
    int i = blockIdx.x * blockDim.x + threadIdx.x;
    if (i >= K * N) return;
    int k = i / N, n = i % N;
    __half h, l;
    split_h(W[i], h, l);
    hi[n * K + k] = h;
    lo[n * K + k] = l;
}

// out[p] = bp2  (pre-init for GEMM3's fused dot epilogue)
__global__ void init_out(float* __restrict__ out, const float* __restrict__ bp2) {
    int i = blockIdx.x * blockDim.x + threadIdx.x;
    if (i < N_PAIRS) out[i] = bp2[0];
}

// ---------------- SpMM: warp-per-node, wide gathers, shuffle indices --------
// H=256: lane gathers uint4 (8 halves).  H=128: lane gathers uint2 (4 halves).
// OUT: 0 = fp32 (+bias), 2 = fp16.
template <int H, int OUT>
__global__ void __launch_bounds__(256, 8)
spmm_warp(const __half* __restrict__ x,
          float* __restrict__ yf,
          __half* __restrict__ yh,
          const int* __restrict__ cols,
          const float* __restrict__ vals,
          const float* __restrict__ bias) {
    constexpr int PER = H / 32;     // halves per lane (8 or 4)
    const int lane = threadIdx.x & 31;
    const int n = blockIdx.x * 8 + (threadIdx.x >> 5);
    if (n >= N_NODES) return;

    int e  = g_rowptr[n];
    const int e1 = g_rowptr[n + 1];

    float acc[PER];
#pragma unroll
    for (int k = 0; k < PER; k++) acc[k] = 0.f;

    // full 32-edge batches: coalesced c/v load, shuffle-broadcast
    for (; e + 32 <= e1; e += 32) {
        int   c = __ldg(cols + e + lane);
        float v = __ldg(vals + e + lane);
#pragma unroll 8
        for (int j = 0; j < 32; j++) {
            int   cj = __shfl_sync(0xffffffffu, c, j);
            float vj = __shfl_sync(0xffffffffu, v, j);
            if (PER == 8) {
                uint4 q = __ldg(reinterpret_cast<const uint4*>(x) +
                                (size_t)cj * (H / 8) + lane);
                float2 f0 = h2f2(q.x), f1 = h2f2(q.y), f2 = h2f2(q.z), f3 = h2f2(q.w);
                acc[0] += vj * f0.x; acc[1] += vj * f0.y;
                acc[2] += vj * f1.x; acc[3] += vj * f1.y;
                acc[4 % PER] += vj * f2.x; acc[5 % PER] += vj * f2.y;
                acc[6 % PER] += vj * f3.x; acc[7 % PER] += vj * f3.y;
            } else {
                uint2 q = __ldg(reinterpret_cast<const uint2*>(x) +
                                (size_t)cj * (H / 4) + lane);
                float2 f0 = h2f2(q.x), f1 = h2f2(q.y);
                acc[0] += vj * f0.x; acc[1] += vj * f0.y;
                acc[2 % PER] += vj * f1.x; acc[3 % PER] += vj * f1.y;
            }
        }
    }
    // remainder
    int rem = e1 - e;
    if (rem > 0) {
        int   c = (lane < rem) ? __ldg(cols + e + lane) : 0;
        float v = (lane < rem) ? __ldg(vals + e + lane) : 0.f;
        for (int j = 0; j < rem; j++) {
            int   cj = __shfl_sync(0xffffffffu, c, j);
            float vj = __shfl_sync(0xffffffffu, v, j);
            if (PER == 8) {
                uint4 q = __ldg(reinterpret_cast<const uint4*>(x) +
                                (size_t)cj * (H / 8) + lane);
                float2 f0 = h2f2(q.x), f1 = h2f2(q.y), f2 = h2f2(q.z), f3 = h2f2(q.w);
                acc[0] += vj * f0.x; acc[1] += vj * f0.y;
                acc[2] += vj * f1.x; acc[3] += vj * f1.y;
                acc[4 % PER] += vj * f2.x; acc[5 % PER] += vj * f2.y;
                acc[6 % PER] += vj * f3.x; acc[7 % PER] += vj * f3.y;
            } else {
                uint2 q = __ldg(reinterpret_cast<const uint2*>(x) +
                                (size_t)cj * (H / 4) + lane);
                float2 f0 = h2f2(q.x), f1 = h2f2(q.y);
                acc[0] += vj * f0.x; acc[1] += vj * f0.y;
                acc[2 % PER] += vj * f1.x; acc[3 % PER] += vj * f1.y;
            }
        }
    }

    if (OUT == 0) {
#pragma unroll
        for (int k = 0; k < PER; k++)
            if (bias) acc[k] += __ldg(bias + lane * PER + k);
#pragma unroll
        for (int k = 0; k < PER; k += 4) {
            float4 o = make_float4(acc[k], acc[k + 1],
                                   acc[(k + 2) % PER], acc[(k + 3) % PER]);
            *reinterpret_cast<float4*>(yf + (size_t)n * H + lane * PER + k) = o;
        }
    } else {
        // pack PER halves
        uint32_t p[PER / 2];
#pragma unroll
        for (int k = 0; k < PER / 2; k++) {
            __half2 t = __floats2half2_rn(acc[2 * k], acc[2 * k + 1]);
            p[k] = *reinterpret_cast<uint32_t*>(&t);
        }
        if (PER == 8) {
            uint4 o = make_uint4(p[0], p[1], p[2 % (PER / 2)], p[3 % (PER / 2)]);
            *reinterpret_cast<uint4*>(yh + (size_t)n * H + lane * 8) = o;
        } else {
            uint2 o = make_uint2(p[0], p[1 % (PER / 2)]);
            *reinterpret_cast<uint2*>(yh + (size_t)n * H + lane * 4) = o;
        }
    }
}

// ===================== HMMA GEMM (fp16 A x fp16-split W, 2 products) ========
// C[M, NTOT] = A[M, KTOT] @ W^T  (A fp16; W fp16 hi/lo, shape [NTOT, KTOT])
// CTA tile 128(M) x 128(N), 8 warps in 4(M) x 2(N), warp tile 32x64,
// kc=32, 2-stage cp.async.
// MODE: 1 = bias+relu fp16 out; 3 = fp16 out;
//       4 = bias+relu, dot with Wp2v, atomicAdd into Cf (pre-initialized).
template <int KTOT, int NTOT, int MODE>
__global__ void __launch_bounds__(256, 2)
gemm_mma(const __half* __restrict__ Ah_,
         const __half* __restrict__ Whi,
         const __half* __restrict__ Wlo,
         float* __restrict__ Cf,
         __half* __restrict__ Ch,
         const float* __restrict__ bias,
         const float* __restrict__ Wp2v, int M) {
    constexpr int KC = 32;
    constexpr int NS = KTOT / KC;
    constexpr int ST_A  = 0;
    constexpr int ST_WH = 8192;
    constexpr int ST_WL = 16384;
    constexpr int STAGE = 24576;

    extern __shared__ __align__(128) char smem[];
    const uint32_t sb = smem_u32(smem);

    const int tid  = threadIdx.x;
    const int lane = tid & 31;
    const int wm   = (tid >> 5) & 3;
    const int wn   = tid >> 7;
    const int m0   = blockIdx.x * 128;
    const int n0   = blockIdx.y * 128;

    auto load_stage = [&](int ks) {
        const int k0 = ks * KC;
        const uint32_t base = sb + (uint32_t)(ks & 1) * STAGE;
#pragma unroll
        for (int i = 0; i < 2; i++) {
            int id  = tid + i * 256;
            int row = id >> 2;
            int c   = id & 3;
            uint32_t soff = (uint32_t)(row * 64 + ((c ^ ((row >> 1) & 3)) << 4));
            int rowa = min(m0 + row, M - 1);
            cp16(base + ST_A + soff, Ah_ + (size_t)rowa * KTOT + k0 + c * 8);
            size_t goff = (size_t)(n0 + row) * KTOT + k0 + c * 8;
            cp16(base + ST_WH + soff, Whi + goff);
            cp16(base + ST_WL + soff, Wlo + goff);
        }
    };

    float acc[2][8][4];
#pragma unroll
    for (int a = 0; a < 2; a++)
#pragma unroll
        for (int b = 0; b < 8; b++)
#pragma unroll
            for (int c = 0; c < 4; c++) acc[a][b][c] = 0.f;

    const int lrow  = (lane & 7) + ((lane >> 3) & 1) * 8;
    const int khalf = lane >> 4;

    load_stage(0);
    CP_COMMIT();

    for (int ks = 0; ks < NS; ks++) {
        if (ks + 1 < NS) load_stage(ks + 1);
        CP_COMMIT();
        CP_WAIT1();
        __syncthreads();

        const uint32_t base = sb + (uint32_t)(ks & 1) * STAGE;
#pragma unroll
        for (int kk = 0; kk < 2; kk++) {
            const int c = kk * 2 + khalf;
            uint32_t ah[2][4];
#pragma unroll
            for (int mi = 0; mi < 2; mi++) {
                int row = wm * 32 + mi * 16 + lrow;
                uint32_t off = (uint32_t)(row * 64 + ((c ^ ((row >> 1) & 3)) << 4));
                ldsm4(ah[mi][0], ah[mi][1], ah[mi][2], ah[mi][3], base + ST_A + off);
            }
            uint32_t bh[4][4], bl[4][4];
#pragma unroll
            for (int ng = 0; ng < 4; ng++) {
                int row = wn * 64 + ng * 16 + lrow;
                uint32_t off = (uint32_t)(row * 64 + ((c ^ ((row >> 1) & 3)) << 4));
                ldsm4(bh[ng][0], bh[ng][1], bh[ng][2], bh[ng][3], base + ST_WH + off);
                ldsm4(bl[ng][0], bl[ng][1], bl[ng][2], bl[ng][3], base + ST_WL + off);
            }
#pragma unroll
            for (int mi = 0; mi < 2; mi++)
#pragma unroll
                for (int ng = 0; ng < 4; ng++)
#pragma unroll
                    for (int sub = 0; sub < 2; sub++) {
                        int ni = ng * 2 + sub;
                        float* d = acc[mi][ni];
                        mma_h(d[0], d[1], d[2], d[3],
                              ah[mi][0], ah[mi][1], ah[mi][2], ah[mi][3],
                              bh[ng][sub], bh[ng][sub + 2]);
                        mma_h(d[0], d[1], d[2], d[3],
                              ah[mi][0], ah[mi][1], ah[mi][2], ah[mi][3],
                              bl[ng][sub], bl[ng][sub + 2]);
                    }
        }
        __syncthreads();
    }

    // ---- epilogue ----
    if (MODE == 4) {
#pragma unroll
        for (int mi = 0; mi < 2; mi++) {
            float s0 = 0.f, s1 = 0.f;
#pragma unroll
            for (int ni = 0; ni < 8; ni++) {
                int col = n0 + wn * 64 + ni * 8 + 2 * (lane & 3);
                float b0 = __ldg(bias + col),  b1 = __ldg(bias + col + 1);
                float w0 = __ldg(Wp2v + col),  w1 = __ldg(Wp2v + col + 1);
                s0 += fmaxf(acc[mi][ni][0] + b0, 0.f) * w0
                    + fmaxf(acc[mi][ni][1] + b1, 0.f) * w1;
                s1 += fmaxf(acc[mi][ni][2] + b0, 0.f) * w0
                    + fmaxf(acc[mi][ni][3] + b1, 0.f) * w1;
            }
            s0 += __shfl_xor_sync(0xffffffffu, s0, 1);
            s0 += __shfl_xor_sync(0xffffffffu, s0, 2);
            s1 += __shfl_xor_sync(0xffffffffu, s1, 1);
            s1 += __shfl_xor_sync(0xffffffffu, s1, 2);
            if ((lane & 3) == 0) {
                int r0 = m0 + wm * 32 + mi * 16 + (lane >> 2);
                int r1 = r0 + 8;
                if (r0 < M) atomicAdd(Cf + r0, s0);
                if (r1 < M) atomicAdd(Cf + r1, s1);
            }
        }
        return;
    }
#pragma unroll
    for (int mi = 0; mi < 2; mi++) {
        int r0 = m0 + wm * 32 + mi * 16 + (lane >> 2);
        int r1 = r0 + 8;
#pragma unroll
        for (int ni = 0; ni < 8; ni++) {
            int col = n0 + wn * 64 + ni * 8 + 2 * (lane & 3);
            float v0 = acc[mi][ni][0], v1 = acc[mi][ni][1];
            float v2 = acc[mi][ni][2], v3 = acc[mi][ni][3];
            if (MODE == 1) {
                float b0 = __ldg(bias + col), b1 = __ldg(bias + col + 1);
                v0 = fmaxf(v0 + b0, 0.f); v1 = fmaxf(v1 + b1, 0.f);
                v2 = fmaxf(v2 + b0, 0.f); v3 = fmaxf(v3 + b1, 0.f);
            }
            if (r0 < M) {
                __half2 p = __floats2half2_rn(v0, v1);
                *reinterpret_cast<uint32_t*>(Ch + (size_t)r0 * NTOT + col) =
                    *reinterpret_cast<uint32_t*>(&p);
            }
            if (r1 < M) {
                __half2 p = __floats2half2_rn(v2, v3);
                *reinterpret_cast<uint32_t*>(Ch + (size_t)r1 * NTOT + col) =
                    *reinterpret_cast<uint32_t*>(&p);
            }
        }
    }
}

// ---------------- feat = [z[s], z[d], z[s]*z[d]] (fp16) ---------------------
__global__ void build_feat(const int* __restrict__ pairs) {
    int p = blockIdx.x;
    int j = threadIdx.x;        // 0..383
    int s = pairs[p];
    int d = pairs[N_PAIRS + p];
    float v;
    if (j < EMB)          v = g_z[s * EMB + j];
    else if (j < 2 * EMB) v = g_z[d * EMB + (j - EMB)];
    else {
        int jj = j - 2 * EMB;
        v = g_z[s * EMB + jj] * g_z[d * EMB + jj];
    }
    g_feat[(size_t)p * (3 * EMB) + j] = __float2half(v);
}

// ===========================================================================
extern "C" void kernel_launch(void* const* d_in, const int* in_sizes, int n_in,
                              void* d_out, int out_size) {
    const int*   tids     = (const int*)  d_in[0];
    const int*   rows     = (const int*)  d_in[1];
    const int*   cols     = (const int*)  d_in[2];
    const float* vals     = (const float*)d_in[3];
    const int*   pairs    = (const int*)  d_in[4];
    const float* node_emb = (const float*)d_in[5];
    const float* type_emb = (const float*)d_in[6];
    const float* W1  = (const float*)d_in[7];
    const float* b1  = (const float*)d_in[8];
    const float* W2  = (const float*)d_in[9];
    const float* b2  = (const float*)d_in[10];
    const float* Wp1 = (const float*)d_in[11];
    const float* bp1 = (const float*)d_in[12];
    const float* Wp2 = (const float*)d_in[13];
    const float* bp2 = (const float*)d_in[14];
    float* out = (float*)d_out;

    void *pxh, *paxh, *phh, *phwh, *pz, *pf;
    void *w1h, *w1l, *w2h, *w2l, *wp1h, *wp1l;
    cudaGetSymbolAddress(&pxh,  g_xh);
    cudaGetSymbolAddress(&paxh, g_axh);
    cudaGetSymbolAddress(&phh,  g_hh);
    cudaGetSymbolAddress(&phwh, g_hwh);
    cudaGetSymbolAddress(&pz,   g_z);
    cudaGetSymbolAddress(&pf,   g_feat);
    cudaGetSymbolAddress(&w1h,  g_w1hi);  cudaGetSymbolAddress(&w1l, g_w1lo);
    cudaGetSymbolAddress(&w2h,  g_w2hi);  cudaGetSymbolAddress(&w2l, g_w2lo);
    cudaGetSymbolAddress(&wp1h, g_wp1hi); cudaGetSymbolAddress(&wp1l, g_wp1lo);

    constexpr int SMEM = 2 * 24576;   // 48 KB
    cudaFuncSetAttribute(gemm_mma<256, 256, 1>,
                         cudaFuncAttributeMaxDynamicSharedMemorySize, SMEM);
    cudaFuncSetAttribute(gemm_mma<256, 128, 3>,
                         cudaFuncAttributeMaxDynamicSharedMemorySize, SMEM);
    cudaFuncSetAttribute(gemm_mma<384, 128, 4>,
                         cudaFuncAttributeMaxDynamicSharedMemorySize, SMEM);

    // 0. weight prep (transpose + fp16 split)
    prep_w<<<(HID * HID + 255) / 256, 256>>>(W1, (__half*)w1h, (__half*)w1l, HID, HID);
    prep_w<<<(HID * EMB + 255) / 256, 256>>>(W2, (__half*)w2h, (__half*)w2l, HID, EMB);
    prep_w<<<(3 * EMB * EMB + 255) / 256, 256>>>(Wp1, (__half*)wp1h, (__half*)wp1l, 3 * EMB, EMB);

    // 1. row_ptr (edge-boundary scatter)
    build_rowptr<<<(N_EDGES + 255) / 256, 256>>>(rows);
    // 2. x = fp16(node_emb + type_emb[type])
    add_emb<<<(N_NODES * HID / 4 + 255) / 256, 256>>>(node_emb, type_emb, tids);
    // 3. ax = spmm(x) -> fp16   [warp-per-node, uint4 gather]
    spmm_warp<HID, 2><<<(N_NODES + 7) / 8, 256>>>(
        (const __half*)pxh, nullptr, (__half*)paxh, cols, vals, nullptr);
    // 4. h = relu(ax @ W1 + b1) -> fp16   [HMMA 128x128]
    {
        dim3 grid((N_NODES + 127) / 128, HID / 128);
        gemm_mma<256, 256, 1><<<grid, 256, SMEM>>>(
            (const __half*)paxh, (const __half*)w1h, (const __half*)w1l,
            nullptr, (__half*)phh, b1, nullptr, N_NODES);
    }
    // 5. hw = h @ W2 -> fp16   [HMMA 128x128]
    {
        dim3 grid((N_NODES + 127) / 128, EMB / 128);
        gemm_mma<256, 128, 3><<<grid, 256, SMEM>>>(
            (const __half*)phh, (const __half*)w2h, (const __half*)w2l,
            nullptr, (__half*)phwh, nullptr, nullptr, N_NODES);
    }
    // 6. z = spmm(hw) + b2  (fp32)   [warp-per-node, uint2 gather]
    spmm_warp<EMB, 0><<<(N_NODES + 7) / 8, 256>>>(
        (const __half*)phwh, (float*)pz, nullptr, cols, vals, b2);
    // 7. feat (fp16)
    build_feat<<<N_PAIRS, 3 * EMB>>>(pairs);
    // 8. out = relu(feat @ Wp1 + bp1) @ Wp2 + bp2   [HMMA 128x128 + fused dot]
    init_out<<<(N_PAIRS + 255) / 256, 256>>>(out, bp2);
    {
        dim3 grid((N_PAIRS + 127) / 128, EMB / 128);
        gemm_mma<384, 128, 4><<<grid, 256, SMEM>>>(
            (const __half*)pf, (const __half*)wp1h, (const __half*)wp1l,
            out, nullptr, bp1, Wp2, N_PAIRS);
    }
}

// round 9
// speedup vs baseline: 3.2981x; 1.2283x over previous
#include <cuda_runtime.h>
#include <cuda_fp16.h>
#include <cstdint>

#define N_NODES 100000
#define N_EDGES 3200000
#define HID 256
#define EMB 128
#define N_PAIRS 100000

// ===================== scratch (device globals) =============================
__device__ __half g_xh [N_NODES * HID];         // spmm1 input (fp16)
__device__ __half g_axh[N_NODES * HID];         // spmm1 out = GEMM1 A (fp16)
__device__ __half g_hh [N_NODES * HID];         // GEMM1 out = GEMM2 A (fp16)
__device__ __half g_hwh[N_NODES * EMB];         // GEMM2 out (fp16, feeds spmm2)
__device__ float  g_z  [N_NODES * EMB];         // spmm2 out (fp32)
__device__ int    g_rowptr[N_NODES + 1];
// transposed + fp16-split weights: [N][K]
__device__ __half g_w1hi[HID * HID],      g_w1lo[HID * HID];
__device__ __half g_w2hi[EMB * HID],      g_w2lo[EMB * HID];
__device__ __half g_wp1hi[EMB * 3 * EMB], g_wp1lo[EMB * 3 * EMB];

// ===================== helpers ==============================================
__device__ __forceinline__ uint32_t smem_u32(const void* p) {
    uint32_t a;
    asm("{ .reg .u64 t; cvta.to.shared.u64 t, %1; cvt.u32.u64 %0, t; }"
        : "=r"(a) : "l"(p));
    return a;
}
__device__ __forceinline__ void cp16(uint32_t dst, const void* src) {
    asm volatile("cp.async.cg.shared.global [%0], [%1], 16;" :: "r"(dst), "l"(src));
}
#define CP_COMMIT() asm volatile("cp.async.commit_group;" ::: "memory")
#define CP_WAIT1()  asm volatile("cp.async.wait_group 1;" ::: "memory")

__device__ __forceinline__ void ldsm4(uint32_t& r0, uint32_t& r1,
                                      uint32_t& r2, uint32_t& r3, uint32_t addr) {
    asm volatile("ldmatrix.sync.aligned.m8n8.x4.shared.b16 {%0,%1,%2,%3}, [%4];"
                 : "=r"(r0), "=r"(r1), "=r"(r2), "=r"(r3) : "r"(addr));
}
__device__ __forceinline__ void mma_h(float& d0, float& d1, float& d2, float& d3,
                                      uint32_t a0, uint32_t a1, uint32_t a2, uint32_t a3,
                                      uint32_t b0, uint32_t b1) {
    asm volatile(
        "mma.sync.aligned.m16n8k16.row.col.f32.f16.f16.f32 "
        "{%0,%1,%2,%3}, {%4,%5,%6,%7}, {%8,%9}, {%0,%1,%2,%3};"
        : "+f"(d0), "+f"(d1), "+f"(d2), "+f"(d3)
        : "r"(a0), "r"(a1), "r"(a2), "r"(a3), "r"(b0), "r"(b1));
}
__device__ __forceinline__ void split_h(float v, __half& h, __half& l) {
    h = __float2half(v);
    l = __float2half(v - __half2float(h));
}
__device__ __forceinline__ float2 h2f2(uint32_t u) {
    return __half22float2(*reinterpret_cast<__half2*>(&u));
}
__device__ __forceinline__ uint32_t pkh2(float a, float b) {
    __half2 t = __floats2half2_rn(a, b);
    return *reinterpret_cast<uint32_t*>(&t);
}

// ===================== small kernels ========================================
// rowptr via edge-boundary scatter (rows sorted ascending)
__global__ void build_rowptr(const int* __restrict__ rows) {
    int e = blockIdx.x * blockDim.x + threadIdx.x;
    if (e >= N_EDGES) return;
    int r  = rows[e];
    int rn = (e + 1 < N_EDGES) ? rows[e + 1] : N_NODES;
    if (e == 0)
        for (int n = 0; n <= r; n++) g_rowptr[n] = 0;
    for (int n = r + 1; n <= rn; n++) g_rowptr[n] = e + 1;
}

// x = fp16(node_emb + type_emb[type])
__global__ void add_emb(const float* __restrict__ node_emb,
                        const float* __restrict__ type_emb,
                        const int* __restrict__ tids) {
    int i = blockIdx.x * blockDim.x + threadIdx.x;          // float4 index
    const int NV = N_NODES * HID / 4;
    if (i >= NV) return;
    int n  = i / (HID / 4);
    int k4 = i % (HID / 4);
    int t  = tids[n];
    float4 a = reinterpret_cast<const float4*>(node_emb)[i];
    float4 b = reinterpret_cast<const float4*>(type_emb)[t * (HID / 4) + k4];
    reinterpret_cast<uint2*>(g_xh)[i] =
        make_uint2(pkh2(a.x + b.x, a.y + b.y), pkh2(a.z + b.z, a.w + b.w));
}

// all 3 weights: W [K,N] fp32 -> Wt_hi/Wt_lo [N,K] fp16 split, one launch
__global__ void prep_w_all(const float* __restrict__ W1, const float* __restrict__ W2,
                           const float* __restrict__ Wp1) {
    int i = blockIdx.x * blockDim.x + threadIdx.x;
    const int S1 = HID * HID;            // W1: K=256,N=256
    const int S2 = S1 + HID * EMB;       // W2: K=256,N=128
    const int S3 = S2 + 3 * EMB * EMB;   // Wp1: K=384,N=128
    const float* W; __half *hi, *lo; int K, N, j;
    if (i < S1)      { W = W1;  hi = g_w1hi;  lo = g_w1lo;  K = HID;     N = HID; j = i; }
    else if (i < S2) { W = W2;  hi = g_w2hi;  lo = g_w2lo;  K = HID;     N = EMB; j = i - S1; }
    else if (i < S3) { W = Wp1; hi = g_wp1hi; lo = g_wp1lo; K = 3 * EMB; N = EMB; j = i - S2; }
    else return;
    int k = j / N, n = j % N;
    __half h, l;
    split_h(W[j], h, l);
    hi[n * K + k] = h;
    lo[n * K + k] = l;
}

// out[p] = bp2  (pre-init for GEMM3's fused dot epilogue)
__global__ void init_out(float* __restrict__ out, const float* __restrict__ bp2) {
    int i = blockIdx.x * blockDim.x + threadIdx.x;
    if (i < N_PAIRS) out[i] = bp2[0];
}

// ---------------- SpMM: warp-per-node, wide gathers, shuffle indices --------
// H=256: lane gathers uint4 (8 halves).  H=128: lane gathers uint2 (4 halves).
// OUT: 0 = fp32 (+bias), 2 = fp16.
template <int H, int OUT>
__global__ void __launch_bounds__(256, 4)
spmm_warp(const __half* __restrict__ x,
          float* __restrict__ yf,
          __half* __restrict__ yh,
          const int* __restrict__ cols,
          const float* __restrict__ vals,
          const float* __restrict__ bias) {
    constexpr int PER = H / 32;     // halves per lane (8 or 4)
    const int lane = threadIdx.x & 31;
    const int n = blockIdx.x * 8 + (threadIdx.x >> 5);
    if (n >= N_NODES) return;

    int e  = g_rowptr[n];
    const int e1 = g_rowptr[n + 1];

    float acc[PER];
#pragma unroll
    for (int k = 0; k < PER; k++) acc[k] = 0.f;

    // full 32-edge batches: coalesced c/v load, shuffle-broadcast
    for (; e + 32 <= e1; e += 32) {
        int   c = __ldg(cols + e + lane);
        float v = __ldg(vals + e + lane);
#pragma unroll 8
        for (int j = 0; j < 32; j++) {
            int   cj = __shfl_sync(0xffffffffu, c, j);
            float vj = __shfl_sync(0xffffffffu, v, j);
            if (PER == 8) {
                uint4 q = __ldg(reinterpret_cast<const uint4*>(x) +
                                (size_t)cj * (H / 8) + lane);
                float2 f0 = h2f2(q.x), f1 = h2f2(q.y), f2 = h2f2(q.z), f3 = h2f2(q.w);
                acc[0] += vj * f0.x; acc[1] += vj * f0.y;
                acc[2] += vj * f1.x; acc[3] += vj * f1.y;
                acc[4 % PER] += vj * f2.x; acc[5 % PER] += vj * f2.y;
                acc[6 % PER] += vj * f3.x; acc[7 % PER] += vj * f3.y;
            } else {
                uint2 q = __ldg(reinterpret_cast<const uint2*>(x) +
                                (size_t)cj * (H / 4) + lane);
                float2 f0 = h2f2(q.x), f1 = h2f2(q.y);
                acc[0] += vj * f0.x; acc[1] += vj * f0.y;
                acc[2 % PER] += vj * f1.x; acc[3 % PER] += vj * f1.y;
            }
        }
    }
    // remainder
    int rem = e1 - e;
    if (rem > 0) {
        int   c = (lane < rem) ? __ldg(cols + e + lane) : 0;
        float v = (lane < rem) ? __ldg(vals + e + lane) : 0.f;
        for (int j = 0; j < rem; j++) {
            int   cj = __shfl_sync(0xffffffffu, c, j);
            float vj = __shfl_sync(0xffffffffu, v, j);
            if (PER == 8) {
                uint4 q = __ldg(reinterpret_cast<const uint4*>(x) +
                                (size_t)cj * (H / 8) + lane);
                float2 f0 = h2f2(q.x), f1 = h2f2(q.y), f2 = h2f2(q.z), f3 = h2f2(q.w);
                acc[0] += vj * f0.x; acc[1] += vj * f0.y;
                acc[2] += vj * f1.x; acc[3] += vj * f1.y;
                acc[4 % PER] += vj * f2.x; acc[5 % PER] += vj * f2.y;
                acc[6 % PER] += vj * f3.x; acc[7 % PER] += vj * f3.y;
            } else {
                uint2 q = __ldg(reinterpret_cast<const uint2*>(x) +
                                (size_t)cj * (H / 4) + lane);
                float2 f0 = h2f2(q.x), f1 = h2f2(q.y);
                acc[0] += vj * f0.x; acc[1] += vj * f0.y;
                acc[2 % PER] += vj * f1.x; acc[3 % PER] += vj * f1.y;
            }
        }
    }

    if (OUT == 0) {
#pragma unroll
        for (int k = 0; k < PER; k++)
            if (bias) acc[k] += __ldg(bias + lane * PER + k);
#pragma unroll
        for (int k = 0; k < PER; k += 4) {
            float4 o = make_float4(acc[k], acc[k + 1],
                                   acc[(k + 2) % PER], acc[(k + 3) % PER]);
            *reinterpret_cast<float4*>(yf + (size_t)n * H + lane * PER + k) = o;
        }
    } else {
        uint32_t p[PER / 2];
#pragma unroll
        for (int k = 0; k < PER / 2; k++)
            p[k] = pkh2(acc[2 * k], acc[2 * k + 1]);
        if (PER == 8) {
            uint4 o = make_uint4(p[0], p[1], p[2 % (PER / 2)], p[3 % (PER / 2)]);
            *reinterpret_cast<uint4*>(yh + (size_t)n * H + lane * 8) = o;
        } else {
            uint2 o = make_uint2(p[0], p[1 % (PER / 2)]);
            *reinterpret_cast<uint2*>(yh + (size_t)n * H + lane * 4) = o;
        }
    }
}

// ===================== HMMA GEMM (fp16 A x fp16-split W, 2 products) ========
// C[M, NTOT] = A[M, KTOT] @ W^T  (W fp16 hi/lo, shape [NTOT, KTOT])
// CTA tile 128(M) x 128(N), 8 warps 4x2, warp tile 32x64, kc=32, 2-stage.
// MODE 1: A from Ah_ (fp16); bias+relu fp16 out.
// MODE 3: A from Ah_ (fp16); fp16 out.
// MODE 4: FUSED FEAT — A built on the fly from z fp32 via pairs
//         (seg = chunk/4: 0=z[s], 1=z[d], 2=z[s]*z[d], fp16-rounded exactly
//          like the old build_feat); bias+relu, dot Wp2v, atomicAdd into Cf.
template <int KTOT, int NTOT, int MODE>
__global__ void __launch_bounds__(256, 2)
gemm_mma(const __half* __restrict__ Ah_,
         const __half* __restrict__ Whi,
         const __half* __restrict__ Wlo,
         float* __restrict__ Cf,
         __half* __restrict__ Ch,
         const float* __restrict__ bias,
         const float* __restrict__ Wp2v,
         const float* __restrict__ zf,
         const int* __restrict__ pairs, int M) {
    constexpr int KC = 32;
    constexpr int NS = KTOT / KC;
    constexpr int ST_A  = 0;
    constexpr int ST_WH = 8192;
    constexpr int ST_WL = 16384;
    constexpr int STAGE = 24576;

    extern __shared__ __align__(128) char smem[];
    const uint32_t sb = smem_u32(smem);

    const int tid  = threadIdx.x;
    const int lane = tid & 31;
    const int wm   = (tid >> 5) & 3;
    const int wn   = tid >> 7;
    const int m0   = blockIdx.x * 128;
    const int n0   = blockIdx.y * 128;

    auto load_stage = [&](int ks) {
        const int k0 = ks * KC;
        const uint32_t base = sb + (uint32_t)(ks & 1) * STAGE;
#pragma unroll
        for (int i = 0; i < 2; i++) {
            int id  = tid + i * 256;           // 0..511
            int row = id >> 2;                 // 0..127
            int c   = id & 3;
            uint32_t soff = (uint32_t)(row * 64 + ((c ^ ((row >> 1) & 3)) << 4));
            if (MODE == 4) {
                // fused feat: build 8 fp16 cols from z fp32
                int p = min(m0 + row, M - 1);
                int seg  = ks >> 2;            // 0=s, 1=d, 2=prod
                int kloc = (ks & 3) * KC + c * 8;   // col within z row
                int s = __ldg(pairs + p);
                int d = __ldg(pairs + N_PAIRS + p);
                uint4 o;
                if (seg == 0) {
                    const float* zp = zf + (size_t)s * EMB + kloc;
                    float4 a0 = *reinterpret_cast<const float4*>(zp);
                    float4 a1 = *reinterpret_cast<const float4*>(zp + 4);
                    o = make_uint4(pkh2(a0.x, a0.y), pkh2(a0.z, a0.w),
                                   pkh2(a1.x, a1.y), pkh2(a1.z, a1.w));
                } else if (seg == 1) {
                    const float* zp = zf + (size_t)d * EMB + kloc;
                    float4 a0 = *reinterpret_cast<const float4*>(zp);
                    float4 a1 = *reinterpret_cast<const float4*>(zp + 4);
                    o = make_uint4(pkh2(a0.x, a0.y), pkh2(a0.z, a0.w),
                                   pkh2(a1.x, a1.y), pkh2(a1.z, a1.w));
                } else {
                    const float* zs = zf + (size_t)s * EMB + kloc;
                    const float* zd = zf + (size_t)d * EMB + kloc;
                    float4 a0 = *reinterpret_cast<const float4*>(zs);
                    float4 a1 = *reinterpret_cast<const float4*>(zs + 4);
                    float4 b0 = *reinterpret_cast<const float4*>(zd);
                    float4 b1 = *reinterpret_cast<const float4*>(zd + 4);
                    o = make_uint4(pkh2(a0.x * b0.x, a0.y * b0.y),
                                   pkh2(a0.z * b0.z, a0.w * b0.w),
                                   pkh2(a1.x * b1.x, a1.y * b1.y),
                                   pkh2(a1.z * b1.z, a1.w * b1.w));
                }
                *reinterpret_cast<uint4*>(smem + ((ks & 1) ? STAGE : 0) + ST_A + soff) = o;
            } else {
                int rowa = min(m0 + row, M - 1);
                cp16(base + ST_A + soff, Ah_ + (size_t)rowa * KTOT + k0 + c * 8);
            }
            size_t goff = (size_t)(n0 + row) * KTOT + k0 + c * 8;
            cp16(base + ST_WH + soff, Whi + goff);
            cp16(base + ST_WL + soff, Wlo + goff);
        }
    };

    float acc[2][8][4];
#pragma unroll
    for (int a = 0; a < 2; a++)
#pragma unroll
        for (int b = 0; b < 8; b++)
#pragma unroll
            for (int c = 0; c < 4; c++) acc[a][b][c] = 0.f;

    const int lrow  = (lane & 7) + ((lane >> 3) & 1) * 8;
    const int khalf = lane >> 4;

    load_stage(0);
    CP_COMMIT();
    if (MODE == 4) __syncthreads();   // A of stage 0 written synchronously

    for (int ks = 0; ks < NS; ks++) {
        if (ks + 1 < NS) load_stage(ks + 1);
        CP_COMMIT();
        CP_WAIT1();
        __syncthreads();

        const uint32_t base = sb + (uint32_t)(ks & 1) * STAGE;
#pragma unroll
        for (int kk = 0; kk < 2; kk++) {
            const int c = kk * 2 + khalf;
            uint32_t ah[2][4];
#pragma unroll
            for (int mi = 0; mi < 2; mi++) {
                int row = wm * 32 + mi * 16 + lrow;
                uint32_t off = (uint32_t)(row * 64 + ((c ^ ((row >> 1) & 3)) << 4));
                ldsm4(ah[mi][0], ah[mi][1], ah[mi][2], ah[mi][3], base + ST_A + off);
            }
            uint32_t bh[4][4], bl[4][4];
#pragma unroll
            for (int ng = 0; ng < 4; ng++) {
                int row = wn * 64 + ng * 16 + lrow;
                uint32_t off = (uint32_t)(row * 64 + ((c ^ ((row >> 1) & 3)) << 4));
                ldsm4(bh[ng][0], bh[ng][1], bh[ng][2], bh[ng][3], base + ST_WH + off);
                ldsm4(bl[ng][0], bl[ng][1], bl[ng][2], bl[ng][3], base + ST_WL + off);
            }
#pragma unroll
            for (int mi = 0; mi < 2; mi++)
#pragma unroll
                for (int ng = 0; ng < 4; ng++)
#pragma unroll
                    for (int sub = 0; sub < 2; sub++) {
                        int ni = ng * 2 + sub;
                        float* d = acc[mi][ni];
                        mma_h(d[0], d[1], d[2], d[3],
                              ah[mi][0], ah[mi][1], ah[mi][2], ah[mi][3],
                              bh[ng][sub], bh[ng][sub + 2]);
                        mma_h(d[0], d[1], d[2], d[3],
                              ah[mi][0], ah[mi][1], ah[mi][2], ah[mi][3],
                              bl[ng][sub], bl[ng][sub + 2]);
                    }
        }
        __syncthreads();
    }

    // ---- epilogue ----
    if (MODE == 4) {
#pragma unroll
        for (int mi = 0; mi < 2; mi++) {
            float s0 = 0.f, s1 = 0.f;
#pragma unroll
            for (int ni = 0; ni < 8; ni++) {
                int col = n0 + wn * 64 + ni * 8 + 2 * (lane & 3);
                float b0 = __ldg(bias + col),  b1 = __ldg(bias + col + 1);
                float w0 = __ldg(Wp2v + col),  w1 = __ldg(Wp2v + col + 1);
                s0 += fmaxf(acc[mi][ni][0] + b0, 0.f) * w0
                    + fmaxf(acc[mi][ni][1] + b1, 0.f) * w1;
                s1 += fmaxf(acc[mi][ni][2] + b0, 0.f) * w0
                    + fmaxf(acc[mi][ni][3] + b1, 0.f) * w1;
            }
            s0 += __shfl_xor_sync(0xffffffffu, s0, 1);
            s0 += __shfl_xor_sync(0xffffffffu, s0, 2);
            s1 += __shfl_xor_sync(0xffffffffu, s1, 1);
            s1 += __shfl_xor_sync(0xffffffffu, s1, 2);
            if ((lane & 3) == 0) {
                int r0 = m0 + wm * 32 + mi * 16 + (lane >> 2);
                int r1 = r0 + 8;
                if (r0 < M) atomicAdd(Cf + r0, s0);
                if (r1 < M) atomicAdd(Cf + r1, s1);
            }
        }
        return;
    }
#pragma unroll
    for (int mi = 0; mi < 2; mi++) {
        int r0 = m0 + wm * 32 + mi * 16 + (lane >> 2);
        int r1 = r0 + 8;
#pragma unroll
        for (int ni = 0; ni < 8; ni++) {
            int col = n0 + wn * 64 + ni * 8 + 2 * (lane & 3);
            float v0 = acc[mi][ni][0], v1 = acc[mi][ni][1];
            float v2 = acc[mi][ni][2], v3 = acc[mi][ni][3];
            if (MODE == 1) {
                float b0 = __ldg(bias + col), b1 = __ldg(bias + col + 1);
                v0 = fmaxf(v0 + b0, 0.f); v1 = fmaxf(v1 + b1, 0.f);
                v2 = fmaxf(v2 + b0, 0.f); v3 = fmaxf(v3 + b1, 0.f);
            }
            if (r0 < M)
                *reinterpret_cast<uint32_t*>(Ch + (size_t)r0 * NTOT + col) = pkh2(v0, v1);
            if (r1 < M)
                *reinterpret_cast<uint32_t*>(Ch + (size_t)r1 * NTOT + col) = pkh2(v2, v3);
        }
    }
}

// ===========================================================================
extern "C" void kernel_launch(void* const* d_in, const int* in_sizes, int n_in,
                              void* d_out, int out_size) {
    const int*   tids     = (const int*)  d_in[0];
    const int*   rows     = (const int*)  d_in[1];
    const int*   cols     = (const int*)  d_in[2];
    const float* vals     = (const float*)d_in[3];
    const int*   pairs    = (const int*)  d_in[4];
    const float* node_emb = (const float*)d_in[5];
    const float* type_emb = (const float*)d_in[6];
    const float* W1  = (const float*)d_in[7];
    const float* b1  = (const float*)d_in[8];
    const float* W2  = (const float*)d_in[9];
    const float* b2  = (const float*)d_in[10];
    const float* Wp1 = (const float*)d_in[11];
    const float* bp1 = (const float*)d_in[12];
    const float* Wp2 = (const float*)d_in[13];
    const float* bp2 = (const float*)d_in[14];
    float* out = (float*)d_out;

    void *pxh, *paxh, *phh, *phwh, *pz;
    void *w1h, *w1l, *w2h, *w2l, *wp1h, *wp1l;
    cudaGetSymbolAddress(&pxh,  g_xh);
    cudaGetSymbolAddress(&paxh, g_axh);
    cudaGetSymbolAddress(&phh,  g_hh);
    cudaGetSymbolAddress(&phwh, g_hwh);
    cudaGetSymbolAddress(&pz,   g_z);
    cudaGetSymbolAddress(&w1h,  g_w1hi);  cudaGetSymbolAddress(&w1l, g_w1lo);
    cudaGetSymbolAddress(&w2h,  g_w2hi);  cudaGetSymbolAddress(&w2l, g_w2lo);
    cudaGetSymbolAddress(&wp1h, g_wp1hi); cudaGetSymbolAddress(&wp1l, g_wp1lo);

    constexpr int SMEM = 2 * 24576;   // 48 KB
    cudaFuncSetAttribute(gemm_mma<256, 256, 1>,
                         cudaFuncAttributeMaxDynamicSharedMemorySize, SMEM);
    cudaFuncSetAttribute(gemm_mma<256, 128, 3>,
                         cudaFuncAttributeMaxDynamicSharedMemorySize, SMEM);
    cudaFuncSetAttribute(gemm_mma<384, 128, 4>,
                         cudaFuncAttributeMaxDynamicSharedMemorySize, SMEM);

    // 0. weight prep (one launch, transpose + fp16 split)
    {
        int tot = HID * HID + HID * EMB + 3 * EMB * EMB;
        prep_w_all<<<(tot + 255) / 256, 256>>>(W1, W2, Wp1);
    }
    // 1. row_ptr (edge-boundary scatter)
    build_rowptr<<<(N_EDGES + 255) / 256, 256>>>(rows);
    // 2. x = fp16(node_emb + type_emb[type])
    add_emb<<<(N_NODES * HID / 4 + 255) / 256, 256>>>(node_emb, type_emb, tids);
    // 3. ax = spmm(x) -> fp16   [warp-per-node, uint4 gather]
    spmm_warp<HID, 2><<<(N_NODES + 7) / 8, 256>>>(
        (const __half*)pxh, nullptr, (__half*)paxh, cols, vals, nullptr);
    // 4. h = relu(ax @ W1 + b1) -> fp16   [HMMA 128x128]
    {
        dim3 grid((N_NODES + 127) / 128, HID / 128);
        gemm_mma<256, 256, 1><<<grid, 256, SMEM>>>(
            (const __half*)paxh, (const __half*)w1h, (const __half*)w1l,
            nullptr, (__half*)phh, b1, nullptr, nullptr, nullptr, N_NODES);
    }
    // 5. hw = h @ W2 -> fp16   [HMMA 128x128]
    {
        dim3 grid((N_NODES + 127) / 128, EMB / 128);
        gemm_mma<256, 128, 3><<<grid, 256, SMEM>>>(
            (const __half*)phh, (const __half*)w2h, (const __half*)w2l,
            nullptr, (__half*)phwh, nullptr, nullptr, nullptr, nullptr, N_NODES);
    }
    // 6. z = spmm(hw) + b2  (fp32)   [warp-per-node, uint2 gather]
    spmm_warp<EMB, 0><<<(N_NODES + 7) / 8, 256>>>(
        (const __half*)phwh, (float*)pz, nullptr, cols, vals, b2);
    // 7+8. out = relu(feat @ Wp1 + bp1) @ Wp2 + bp2  [fused feat + HMMA + dot]
    init_out<<<(N_PAIRS + 255) / 256, 256>>>(out, bp2);
    {
        dim3 grid((N_PAIRS + 127) / 128, EMB / 128);
        gemm_mma<384, 128, 4><<<grid, 256, SMEM>>>(
            nullptr, (const __half*)wp1h, (const __half*)wp1l,
            out, nullptr, bp1, Wp2, (const float*)pz, pairs, N_PAIRS);
    }
}

// round 10
// speedup vs baseline: 3.4842x; 1.0564x over previous
#include <cuda_runtime.h>
#include <cuda_fp16.h>
#include <cstdint>

#define N_NODES 100000
#define N_EDGES 3200000
#define HID 256
#define EMB 128
#define N_PAIRS 100000

// ===================== scratch (device globals) =============================
__device__ __half g_xh [N_NODES * HID];         // spmm1 input (fp16)
__device__ __half g_axh[N_NODES * HID];         // spmm1 out = GEMM1 A (fp16)
__device__ __half g_hh [N_NODES * HID];         // GEMM1 out = GEMM2 A (fp16)
__device__ __half g_hwh[N_NODES * EMB];         // GEMM2 out (fp16, feeds spmm2)
__device__ float  g_z  [N_NODES * EMB];         // spmm2 out (fp32)
__device__ int    g_rowptr[N_NODES + 1];
// transposed + fp16-split weights: [N][K]
__device__ __half g_w1hi[HID * HID],      g_w1lo[HID * HID];
__device__ __half g_w2hi[EMB * HID],      g_w2lo[EMB * HID];
__device__ __half g_wp1hi[EMB * 3 * EMB], g_wp1lo[EMB * 3 * EMB];

// ===================== helpers ==============================================
__device__ __forceinline__ uint32_t smem_u32(const void* p) {
    uint32_t a;
    asm("{ .reg .u64 t; cvta.to.shared.u64 t, %1; cvt.u32.u64 %0, t; }"
        : "=r"(a) : "l"(p));
    return a;
}
__device__ __forceinline__ void cp16(uint32_t dst, const void* src) {
    asm volatile("cp.async.cg.shared.global [%0], [%1], 16;" :: "r"(dst), "l"(src));
}
#define CP_COMMIT() asm volatile("cp.async.commit_group;" ::: "memory")
#define CP_WAIT1()  asm volatile("cp.async.wait_group 1;" ::: "memory")

__device__ __forceinline__ void ldsm4(uint32_t& r0, uint32_t& r1,
                                      uint32_t& r2, uint32_t& r3, uint32_t addr) {
    asm volatile("ldmatrix.sync.aligned.m8n8.x4.shared.b16 {%0,%1,%2,%3}, [%4];"
                 : "=r"(r0), "=r"(r1), "=r"(r2), "=r"(r3) : "r"(addr));
}
__device__ __forceinline__ void mma_h(float& d0, float& d1, float& d2, float& d3,
                                      uint32_t a0, uint32_t a1, uint32_t a2, uint32_t a3,
                                      uint32_t b0, uint32_t b1) {
    asm volatile(
        "mma.sync.aligned.m16n8k16.row.col.f32.f16.f16.f32 "
        "{%0,%1,%2,%3}, {%4,%5,%6,%7}, {%8,%9}, {%0,%1,%2,%3};"
        : "+f"(d0), "+f"(d1), "+f"(d2), "+f"(d3)
        : "r"(a0), "r"(a1), "r"(a2), "r"(a3), "r"(b0), "r"(b1));
}
__device__ __forceinline__ void split_h(float v, __half& h, __half& l) {
    h = __float2half(v);
    l = __float2half(v - __half2float(h));
}
__device__ __forceinline__ float2 h2f2(uint32_t u) {
    return __half22float2(*reinterpret_cast<__half2*>(&u));
}
__device__ __forceinline__ uint32_t pkh2(float a, float b) {
    __half2 t = __floats2half2_rn(a, b);
    return *reinterpret_cast<uint32_t*>(&t);
}

// ===================== small kernels ========================================
// rowptr via edge-boundary scatter (rows sorted ascending)
__global__ void build_rowptr(const int* __restrict__ rows) {
    int e = blockIdx.x * blockDim.x + threadIdx.x;
    if (e >= N_EDGES) return;
    int r  = rows[e];
    int rn = (e + 1 < N_EDGES) ? rows[e + 1] : N_NODES;
    if (e == 0)
        for (int n = 0; n <= r; n++) g_rowptr[n] = 0;
    for (int n = r + 1; n <= rn; n++) g_rowptr[n] = e + 1;
}

// x = fp16(node_emb + type_emb[type])
__global__ void add_emb(const float* __restrict__ node_emb,
                        const float* __restrict__ type_emb,
                        const int* __restrict__ tids) {
    int i = blockIdx.x * blockDim.x + threadIdx.x;          // float4 index
    const int NV = N_NODES * HID / 4;
    if (i >= NV) return;
    int n  = i / (HID / 4);
    int k4 = i % (HID / 4);
    int t  = tids[n];
    float4 a = reinterpret_cast<const float4*>(node_emb)[i];
    float4 b = reinterpret_cast<const float4*>(type_emb)[t * (HID / 4) + k4];
    reinterpret_cast<uint2*>(g_xh)[i] =
        make_uint2(pkh2(a.x + b.x, a.y + b.y), pkh2(a.z + b.z, a.w + b.w));
}

// all 3 weights: W [K,N] fp32 -> Wt_hi/Wt_lo [N,K] fp16 split, one launch
__global__ void prep_w_all(const float* __restrict__ W1, const float* __restrict__ W2,
                           const float* __restrict__ Wp1) {
    int i = blockIdx.x * blockDim.x + threadIdx.x;
    const int S1 = HID * HID;
    const int S2 = S1 + HID * EMB;
    const int S3 = S2 + 3 * EMB * EMB;
    const float* W; __half *hi, *lo; int K, N, j;
    if (i < S1)      { W = W1;  hi = g_w1hi;  lo = g_w1lo;  K = HID;     N = HID; j = i; }
    else if (i < S2) { W = W2;  hi = g_w2hi;  lo = g_w2lo;  K = HID;     N = EMB; j = i - S1; }
    else if (i < S3) { W = Wp1; hi = g_wp1hi; lo = g_wp1lo; K = 3 * EMB; N = EMB; j = i - S2; }
    else return;
    int k = j / N, n = j % N;
    __half h, l;
    split_h(W[j], h, l);
    hi[n * K + k] = h;
    lo[n * K + k] = l;
}

// out[p] = bp2  (pre-init for GEMM3's fused dot epilogue)
__global__ void init_out(float* __restrict__ out, const float* __restrict__ bp2) {
    int i = blockIdx.x * blockDim.x + threadIdx.x;
    if (i < N_PAIRS) out[i] = bp2[0];
}

// ---------------- SpMM: warp-per-node, wide gathers, shuffle indices --------
// H=256: lane gathers uint4 (8 halves), unroll 4 (reg-capped for 6 CTAs/SM).
// H=128: lane gathers uint2 (4 halves), unroll 8.
// OUT: 0 = fp32 (+bias), 2 = fp16.
template <int H, int OUT>
__global__ void __launch_bounds__(256, 6)
spmm_warp(const __half* __restrict__ x,
          float* __restrict__ yf,
          __half* __restrict__ yh,
          const int* __restrict__ cols,
          const float* __restrict__ vals,
          const float* __restrict__ bias) {
    constexpr int PER = H / 32;     // halves per lane (8 or 4)
    constexpr int UNR = (PER == 8) ? 4 : 8;
    const int lane = threadIdx.x & 31;
    const int n = blockIdx.x * 8 + (threadIdx.x >> 5);
    if (n >= N_NODES) return;

    int e  = g_rowptr[n];
    const int e1 = g_rowptr[n + 1];

    float acc[PER];
#pragma unroll
    for (int k = 0; k < PER; k++) acc[k] = 0.f;

    // full 32-edge batches: coalesced c/v load, shuffle-broadcast
    for (; e + 32 <= e1; e += 32) {
        int   c = __ldg(cols + e + lane);
        float v = __ldg(vals + e + lane);
#pragma unroll UNR
        for (int j = 0; j < 32; j++) {
            int   cj = __shfl_sync(0xffffffffu, c, j);
            float vj = __shfl_sync(0xffffffffu, v, j);
            if (PER == 8) {
                uint4 q = __ldg(reinterpret_cast<const uint4*>(x) +
                                (size_t)cj * (H / 8) + lane);
                float2 f0 = h2f2(q.x), f1 = h2f2(q.y), f2 = h2f2(q.z), f3 = h2f2(q.w);
                acc[0] += vj * f0.x; acc[1] += vj * f0.y;
                acc[2] += vj * f1.x; acc[3] += vj * f1.y;
                acc[4 % PER] += vj * f2.x; acc[5 % PER] += vj * f2.y;
                acc[6 % PER] += vj * f3.x; acc[7 % PER] += vj * f3.y;
            } else {
                uint2 q = __ldg(reinterpret_cast<const uint2*>(x) +
                                (size_t)cj * (H / 4) + lane);
                float2 f0 = h2f2(q.x), f1 = h2f2(q.y);
                acc[0] += vj * f0.x; acc[1] += vj * f0.y;
                acc[2 % PER] += vj * f1.x; acc[3 % PER] += vj * f1.y;
            }
        }
    }
    // remainder
    int rem = e1 - e;
    if (rem > 0) {
        int   c = (lane < rem) ? __ldg(cols + e + lane) : 0;
        float v = (lane < rem) ? __ldg(vals + e + lane) : 0.f;
        for (int j = 0; j < rem; j++) {
            int   cj = __shfl_sync(0xffffffffu, c, j);
            float vj = __shfl_sync(0xffffffffu, v, j);
            if (PER == 8) {
                uint4 q = __ldg(reinterpret_cast<const uint4*>(x) +
                                (size_t)cj * (H / 8) + lane);
                float2 f0 = h2f2(q.x), f1 = h2f2(q.y), f2 = h2f2(q.z), f3 = h2f2(q.w);
                acc[0] += vj * f0.x; acc[1] += vj * f0.y;
                acc[2] += vj * f1.x; acc[3] += vj * f1.y;
                acc[4 % PER] += vj * f2.x; acc[5 % PER] += vj * f2.y;
                acc[6 % PER] += vj * f3.x; acc[7 % PER] += vj * f3.y;
            } else {
                uint2 q = __ldg(reinterpret_cast<const uint2*>(x) +
                                (size_t)cj * (H / 4) + lane);
                float2 f0 = h2f2(q.x), f1 = h2f2(q.y);
                acc[0] += vj * f0.x; acc[1] += vj * f0.y;
                acc[2 % PER] += vj * f1.x; acc[3 % PER] += vj * f1.y;
            }
        }
    }

    if (OUT == 0) {
#pragma unroll
        for (int k = 0; k < PER; k++)
            if (bias) acc[k] += __ldg(bias + lane * PER + k);
#pragma unroll
        for (int k = 0; k < PER; k += 4) {
            float4 o = make_float4(acc[k], acc[k + 1],
                                   acc[(k + 2) % PER], acc[(k + 3) % PER]);
            *reinterpret_cast<float4*>(yf + (size_t)n * H + lane * PER + k) = o;
        }
    } else {
        uint32_t p[PER / 2];
#pragma unroll
        for (int k = 0; k < PER / 2; k++)
            p[k] = pkh2(acc[2 * k], acc[2 * k + 1]);
        if (PER == 8) {
            uint4 o = make_uint4(p[0], p[1], p[2 % (PER / 2)], p[3 % (PER / 2)]);
            *reinterpret_cast<uint4*>(yh + (size_t)n * H + lane * 8) = o;
        } else {
            uint2 o = make_uint2(p[0], p[1 % (PER / 2)]);
            *reinterpret_cast<uint2*>(yh + (size_t)n * H + lane * 4) = o;
        }
    }
}

// ===================== HMMA GEMM (fp16 A x fp16-split W, 2 products) ========
// C[M, NTOT] = A[M, KTOT] @ W^T  (W fp16 hi/lo, shape [NTOT, KTOT])
// CTA tile 128(M) x 128(N), 8 warps 4x2, warp tile 32x64, kc=32, 2-stage.
// MODE 1: A from Ah_ (fp16); bias+relu fp16 out.
// MODE 3: A from Ah_ (fp16); fp16 out.
// MODE 4: FUSED FEAT — A built on the fly from z fp32 via pairs
//         (seg = chunk/4: 0=z[s], 1=z[d], 2=z[s]*z[d]); bias+relu,
//         dot Wp2v, atomicAdd into Cf (pre-initialized with bp2).
template <int KTOT, int NTOT, int MODE>
__global__ void __launch_bounds__(256, 2)
gemm_mma(const __half* __restrict__ Ah_,
         const __half* __restrict__ Whi,
         const __half* __restrict__ Wlo,
         float* __restrict__ Cf,
         __half* __restrict__ Ch,
         const float* __restrict__ bias,
         const float* __restrict__ Wp2v,
         const float* __restrict__ zf,
         const int* __restrict__ pairs, int M) {
    constexpr int KC = 32;
    constexpr int NS = KTOT / KC;
    constexpr int ST_A  = 0;
    constexpr int ST_WH = 8192;
    constexpr int ST_WL = 16384;
    constexpr int STAGE = 24576;

    extern __shared__ __align__(128) char smem[];
    const uint32_t sb = smem_u32(smem);

    const int tid  = threadIdx.x;
    const int lane = tid & 31;
    const int wm   = (tid >> 5) & 3;
    const int wn   = tid >> 7;
    const int m0   = blockIdx.x * 128;
    const int n0   = blockIdx.y * 128;

    auto load_stage = [&](int ks) {
        const int k0 = ks * KC;
        const uint32_t base = sb + (uint32_t)(ks & 1) * STAGE;
#pragma unroll
        for (int i = 0; i < 2; i++) {
            int id  = tid + i * 256;
            int row = id >> 2;
            int c   = id & 3;
            uint32_t soff = (uint32_t)(row * 64 + ((c ^ ((row >> 1) & 3)) << 4));
            if (MODE == 4) {
                int p = min(m0 + row, M - 1);
                int seg  = ks >> 2;
                int kloc = (ks & 3) * KC + c * 8;
                int s = __ldg(pairs + p);
                int d = __ldg(pairs + N_PAIRS + p);
                uint4 o;
                if (seg == 0) {
                    const float* zp = zf + (size_t)s * EMB + kloc;
                    float4 a0 = *reinterpret_cast<const float4*>(zp);
                    float4 a1 = *reinterpret_cast<const float4*>(zp + 4);
                    o = make_uint4(pkh2(a0.x, a0.y), pkh2(a0.z, a0.w),
                                   pkh2(a1.x, a1.y), pkh2(a1.z, a1.w));
                } else if (seg == 1) {
                    const float* zp = zf + (size_t)d * EMB + kloc;
                    float4 a0 = *reinterpret_cast<const float4*>(zp);
                    float4 a1 = *reinterpret_cast<const float4*>(zp + 4);
                    o = make_uint4(pkh2(a0.x, a0.y), pkh2(a0.z, a0.w),
                                   pkh2(a1.x, a1.y), pkh2(a1.z, a1.w));
                } else {
                    const float* zs = zf + (size_t)s * EMB + kloc;
                    const float* zd = zf + (size_t)d * EMB + kloc;
                    float4 a0 = *reinterpret_cast<const float4*>(zs);
                    float4 a1 = *reinterpret_cast<const float4*>(zs + 4);
                    float4 b0 = *reinterpret_cast<const float4*>(zd);
                    float4 b1 = *reinterpret_cast<const float4*>(zd + 4);
                    o = make_uint4(pkh2(a0.x * b0.x, a0.y * b0.y),
                                   pkh2(a0.z * b0.z, a0.w * b0.w),
                                   pkh2(a1.x * b1.x, a1.y * b1.y),
                                   pkh2(a1.z * b1.z, a1.w * b1.w));
                }
                *reinterpret_cast<uint4*>(smem + ((ks & 1) ? STAGE : 0) + ST_A + soff) = o;
            } else {
                int rowa = min(m0 + row, M - 1);
                cp16(base + ST_A + soff, Ah_ + (size_t)rowa * KTOT + k0 + c * 8);
            }
            size_t goff = (size_t)(n0 + row) * KTOT + k0 + c * 8;
            cp16(base + ST_WH + soff, Whi + goff);
            cp16(base + ST_WL + soff, Wlo + goff);
        }
    };

    float acc[2][8][4];
#pragma unroll
    for (int a = 0; a < 2; a++)
#pragma unroll
        for (int b = 0; b < 8; b++)
#pragma unroll
            for (int c = 0; c < 4; c++) acc[a][b][c] = 0.f;

    const int lrow  = (lane & 7) + ((lane >> 3) & 1) * 8;
    const int khalf = lane >> 4;

    load_stage(0);
    CP_COMMIT();
    if (MODE == 4) __syncthreads();

    for (int ks = 0; ks < NS; ks++) {
        if (ks + 1 < NS) load_stage(ks + 1);
        CP_COMMIT();
        CP_WAIT1();
        __syncthreads();

        const uint32_t base = sb + (uint32_t)(ks & 1) * STAGE;
#pragma unroll
        for (int kk = 0; kk < 2; kk++) {
            const int c = kk * 2 + khalf;
            uint32_t ah[2][4];
#pragma unroll
            for (int mi = 0; mi < 2; mi++) {
                int row = wm * 32 + mi * 16 + lrow;
                uint32_t off = (uint32_t)(row * 64 + ((c ^ ((row >> 1) & 3)) << 4));
                ldsm4(ah[mi][0], ah[mi][1], ah[mi][2], ah[mi][3], base + ST_A + off);
            }
            uint32_t bh[4][4], bl[4][4];
#pragma unroll
            for (int ng = 0; ng < 4; ng++) {
                int row = wn * 64 + ng * 16 + lrow;
                uint32_t off = (uint32_t)(row * 64 + ((c ^ ((row >> 1) & 3)) << 4));
                ldsm4(bh[ng][0], bh[ng][1], bh[ng][2], bh[ng][3], base + ST_WH + off);
                ldsm4(bl[ng][0], bl[ng][1], bl[ng][2], bl[ng][3], base + ST_WL + off);
            }
#pragma unroll
            for (int mi = 0; mi < 2; mi++)
#pragma unroll
                for (int ng = 0; ng < 4; ng++)
#pragma unroll
                    for (int sub = 0; sub < 2; sub++) {
                        int ni = ng * 2 + sub;
                        float* d = acc[mi][ni];
                        mma_h(d[0], d[1], d[2], d[3],
                              ah[mi][0], ah[mi][1], ah[mi][2], ah[mi][3],
                              bh[ng][sub], bh[ng][sub + 2]);
                        mma_h(d[0], d[1], d[2], d[3],
                              ah[mi][0], ah[mi][1], ah[mi][2], ah[mi][3],
                              bl[ng][sub], bl[ng][sub + 2]);
                    }
        }
        __syncthreads();
    }

    // ---- epilogue ----
    if (MODE == 4) {
#pragma unroll
        for (int mi = 0; mi < 2; mi++) {
            float s0 = 0.f, s1 = 0.f;
#pragma unroll
            for (int ni = 0; ni < 8; ni++) {
                int col = n0 + wn * 64 + ni * 8 + 2 * (lane & 3);
                float b0 = __ldg(bias + col),  b1 = __ldg(bias + col + 1);
                float w0 = __ldg(Wp2v + col),  w1 = __ldg(Wp2v + col + 1);
                s0 += fmaxf(acc[mi][ni][0] + b0, 0.f) * w0
                    + fmaxf(acc[mi][ni][1] + b1, 0.f) * w1;
                s1 += fmaxf(acc[mi][ni][2] + b0, 0.f) * w0
                    + fmaxf(acc[mi][ni][3] + b1, 0.f) * w1;
            }
            s0 += __shfl_xor_sync(0xffffffffu, s0, 1);
            s0 += __shfl_xor_sync(0xffffffffu, s0, 2);
            s1 += __shfl_xor_sync(0xffffffffu, s1, 1);
            s1 += __shfl_xor_sync(0xffffffffu, s1, 2);
            if ((lane & 3) == 0) {
                int r0 = m0 + wm * 32 + mi * 16 + (lane >> 2);
                int r1 = r0 + 8;
                if (r0 < M) atomicAdd(Cf + r0, s0);
                if (r1 < M) atomicAdd(Cf + r1, s1);
            }
        }
        return;
    }
#pragma unroll
    for (int mi = 0; mi < 2; mi++) {
        int r0 = m0 + wm * 32 + mi * 16 + (lane >> 2);
        int r1 = r0 + 8;
#pragma unroll
        for (int ni = 0; ni < 8; ni++) {
            int col = n0 + wn * 64 + ni * 8 + 2 * (lane & 3);
            float v0 = acc[mi][ni][0], v1 = acc[mi][ni][1];
            float v2 = acc[mi][ni][2], v3 = acc[mi][ni][3];
            if (MODE == 1) {
                float b0 = __ldg(bias + col), b1 = __ldg(bias + col + 1);
                v0 = fmaxf(v0 + b0, 0.f); v1 = fmaxf(v1 + b1, 0.f);
                v2 = fmaxf(v2 + b0, 0.f); v3 = fmaxf(v3 + b1, 0.f);
            }
            if (r0 < M)
                *reinterpret_cast<uint32_t*>(Ch + (size_t)r0 * NTOT + col) = pkh2(v0, v1);
            if (r1 < M)
                *reinterpret_cast<uint32_t*>(Ch + (size_t)r1 * NTOT + col) = pkh2(v2, v3);
        }
    }
}

// ===========================================================================
extern "C" void kernel_launch(void* const* d_in, const int* in_sizes, int n_in,
                              void* d_out, int out_size) {
    const int*   tids     = (const int*)  d_in[0];
    const int*   rows     = (const int*)  d_in[1];
    const int*   cols     = (const int*)  d_in[2];
    const float* vals     = (const float*)d_in[3];
    const int*   pairs    = (const int*)  d_in[4];
    const float* node_emb = (const float*)d_in[5];
    const float* type_emb = (const float*)d_in[6];
    const float* W1  = (const float*)d_in[7];
    const float* b1  = (const float*)d_in[8];
    const float* W2  = (const float*)d_in[9];
    const float* b2  = (const float*)d_in[10];
    const float* Wp1 = (const float*)d_in[11];
    const float* bp1 = (const float*)d_in[12];
    const float* Wp2 = (const float*)d_in[13];
    const float* bp2 = (const float*)d_in[14];
    float* out = (float*)d_out;

    void *pxh, *paxh, *phh, *phwh, *pz;
    void *w1h, *w1l, *w2h, *w2l, *wp1h, *wp1l;
    cudaGetSymbolAddress(&pxh,  g_xh);
    cudaGetSymbolAddress(&paxh, g_axh);
    cudaGetSymbolAddress(&phh,  g_hh);
    cudaGetSymbolAddress(&phwh, g_hwh);
    cudaGetSymbolAddress(&pz,   g_z);
    cudaGetSymbolAddress(&w1h,  g_w1hi);  cudaGetSymbolAddress(&w1l, g_w1lo);
    cudaGetSymbolAddress(&w2h,  g_w2hi);  cudaGetSymbolAddress(&w2l, g_w2lo);
    cudaGetSymbolAddress(&wp1h, g_wp1hi); cudaGetSymbolAddress(&wp1l, g_wp1lo);

    constexpr int SMEM = 2 * 24576;   // 48 KB
    cudaFuncSetAttribute(gemm_mma<256, 256, 1>,
                         cudaFuncAttributeMaxDynamicSharedMemorySize, SMEM);
    cudaFuncSetAttribute(gemm_mma<256, 128, 3>,
                         cudaFuncAttributeMaxDynamicSharedMemorySize, SMEM);
    cudaFuncSetAttribute(gemm_mma<384, 128, 4>,
                         cudaFuncAttributeMaxDynamicSharedMemorySize, SMEM);

    // 0. weight prep (one launch, transpose + fp16 split)
    {
        int tot = HID * HID + HID * EMB + 3 * EMB * EMB;
        prep_w_all<<<(tot + 255) / 256, 256>>>(W1, W2, Wp1);
    }
    // 1. row_ptr (edge-boundary scatter)
    build_rowptr<<<(N_EDGES + 255) / 256, 256>>>(rows);
    // 2. x = fp16(node_emb + type_emb[type])
    add_emb<<<(N_NODES * HID / 4 + 255) / 256, 256>>>(node_emb, type_emb, tids);
    // 3. ax = spmm(x) -> fp16   [warp-per-node, uint4 gather, 6 CTAs/SM]
    spmm_warp<HID, 2><<<(N_NODES + 7) / 8, 256>>>(
        (const __half*)pxh, nullptr, (__half*)paxh, cols, vals, nullptr);
    // 4. h = relu(ax @ W1 + b1) -> fp16   [HMMA 128x128]
    {
        dim3 grid((N_NODES + 127) / 128, HID / 128);
        gemm_mma<256, 256, 1><<<grid, 256, SMEM>>>(
            (const __half*)paxh, (const __half*)w1h, (const __half*)w1l,
            nullptr, (__half*)phh, b1, nullptr, nullptr, nullptr, N_NODES);
    }
    // 5. hw = h @ W2 -> fp16   [HMMA 128x128]
    {
        dim3 grid((N_NODES + 127) / 128, EMB / 128);
        gemm_mma<256, 128, 3><<<grid, 256, SMEM>>>(
            (const __half*)phh, (const __half*)w2h, (const __half*)w2l,
            nullptr, (__half*)phwh, nullptr, nullptr, nullptr, nullptr, N_NODES);
    }
    // 6. z = spmm(hw) + b2  (fp32)   [warp-per-node, uint2 gather]
    spmm_warp<EMB, 0><<<(N_NODES + 7) / 8, 256>>>(
        (const __half*)phwh, (float*)pz, nullptr, cols, vals, b2);
    // 7+8. out = relu(feat @ Wp1 + bp1) @ Wp2 + bp2  [fused feat + HMMA + dot]
    init_out<<<(N_PAIRS + 255) / 256, 256>>>(out, bp2);
    {
        dim3 grid((N_PAIRS + 127) / 128, EMB / 128);
        gemm_mma<384, 128, 4><<<grid, 256, SMEM>>>(
            nullptr, (const __half*)wp1h, (const __half*)wp1l,
            out, nullptr, bp1, Wp2, (const float*)pz, pairs, N_PAIRS);
    }
}